// round 2
// baseline (speedup 1.0000x reference)
#include <cuda_runtime.h>
#include <cuda_bf16.h>
#include <cstdint>

// ---------------- constants ----------------
static constexpr int GX = 100, GY = 100, GZ = 20;
static constexpr int NVOX = GX * GY * GZ;            // 200000
static constexpr int MAXV = 60000, MAXP = 10;
static constexpr int NB_SCAN = (NVOX + 1023) / 1024; // 196
static constexpr int N1 = 10 * 50 * 50;              // 25000
static constexpr int N2 = 5 * 25 * 25;               // 3125
static constexpr int P2D = 625;                      // 25*25

// ---------------- device scratch ----------------
__device__ int           g_count[NVOX];
__device__ float         g_pbuf[(size_t)NVOX * MAXP * 5];
__device__ unsigned char g_m0[NVOX];
__device__ unsigned char g_m1[N1];
__device__ unsigned char g_m2[N2];
__device__ int           g_list0[MAXV];      // hash of kept voxel
__device__ int           g_list0cell[MAXV];  // dense cell index (z*GY+y)*GX+x
__device__ int           g_list1[N1];
__device__ int           g_list2[N2];
__device__ int           g_cntArr[3];        // [0]=nkept [1]=cnt1 [2]=cnt2
__device__ int           g_bsum[NB_SCAN], g_boff[NB_SCAN];

__device__ float g_feat0[(size_t)NVOX * 128];
__device__ float g_feat1[(size_t)NVOX * 64];
__device__ float g_feat2[(size_t)N1 * 128];
__device__ float g_feat3[(size_t)N1 * 128];
__device__ float g_feat4[(size_t)N2 * 256];
__device__ float g_bevin[(size_t)1280 * P2D];
__device__ float g_col1[(size_t)11520 * P2D];
__device__ float g_col2[(size_t)4608 * P2D];
__device__ float g_bev1[(size_t)512 * P2D];

__device__ float g_w1t[27 * 128 * 64];
__device__ float g_w2t[27 * 64 * 128];
__device__ float g_w3t[27 * 128 * 128];
__device__ float g_w4t[27 * 128 * 256];
__device__ float g_wb1t[9 * 1280 * 512];
__device__ float g_wb2t[9 * 512 * 256];
__device__ float g_vfe1t[5 * 32], g_vfe1b[32];
__device__ float g_vfe2t[32 * 128], g_vfe2b[128];
__device__ float g_pad[128];
__device__ float g_bb1[512], g_bb2[256];

// ---------------- zero / init ----------------
__global__ void zero_misc() {
    int i = blockIdx.x * blockDim.x + threadIdx.x;
    if (i < NVOX) { g_count[i] = 0; g_m0[i] = 0; }
    if (i < N1) g_m1[i] = 0;
    if (i < N2) g_m2[i] = 0;
    if (i < 3) g_cntArr[i] = 0;
}

// ---------------- voxelize ----------------
__global__ void scatter_pts(const float* __restrict__ pts, int N) {
    int i = blockIdx.x * blockDim.x + threadIdx.x;
    if (i >= N) return;
    const float* p = pts + (size_t)i * 5;
    float x = p[0], y = p[1], z = p[2];
    if (x == 0.0f) return;
    int ix = (int)floorf(__fdiv_rn(__fsub_rn(x, -51.2f), 1.024f));
    int iy = (int)floorf(__fdiv_rn(__fsub_rn(y, -51.2f), 1.024f));
    int iz = (int)floorf(__fdiv_rn(__fsub_rn(z, -5.0f), 0.4f));
    if (ix < 0 || ix >= GX || iy < 0 || iy >= GY || iz < 0 || iz >= GZ) return;
    int h = ix * (GY * GZ) + iy * GZ + iz;
    int r = atomicAdd(&g_count[h], 1);
    if (r < MAXP) {
        float* d = g_pbuf + ((size_t)h * MAXP + r) * 5;
        d[0] = x; d[1] = y; d[2] = z; d[3] = p[3]; d[4] = p[4];
    }
}

// occupancy rank in hash order == reference 'slot'
__global__ void scan_p1() {
    int b = blockIdx.x, t = threadIdx.x;
    int base = b * 1024 + t * 4;
    int s = 0;
#pragma unroll
    for (int j = 0; j < 4; j++) { int h = base + j; if (h < NVOX && g_count[h] != 0) s++; }
#pragma unroll
    for (int o = 16; o > 0; o >>= 1) s += __shfl_down_sync(0xffffffffu, s, o);
    __shared__ int ws[8];
    if ((t & 31) == 0) ws[t >> 5] = s;
    __syncthreads();
    if (t == 0) { int tot = 0; for (int i = 0; i < 8; i++) tot += ws[i]; g_bsum[b] = tot; }
}

__global__ void scan_p2() {
    if (threadIdx.x == 0) {
        int r = 0;
        for (int i = 0; i < NB_SCAN; i++) { g_boff[i] = r; r += g_bsum[i]; }
        g_cntArr[0] = (r < MAXV) ? r : MAXV;
    }
}

__global__ void scan_p3() {
    int b = blockIdx.x, t = threadIdx.x;
    int base = b * 1024 + t * 4;
    int f[4]; int tsum = 0;
#pragma unroll
    for (int j = 0; j < 4; j++) { int h = base + j; f[j] = (h < NVOX && g_count[h] != 0) ? 1 : 0; tsum += f[j]; }
    int lane = t & 31, wid = t >> 5;
    int incl = tsum;
#pragma unroll
    for (int o = 1; o < 32; o <<= 1) { int v = __shfl_up_sync(0xffffffffu, incl, o); if (lane >= o) incl += v; }
    __shared__ int wsum[8], woff[8];
    if (lane == 31) wsum[wid] = incl;
    __syncthreads();
    if (t == 0) { int r = 0; for (int i = 0; i < 8; i++) { woff[i] = r; r += wsum[i]; } }
    __syncthreads();
    int run = g_boff[b] + woff[wid] + (incl - tsum);
#pragma unroll
    for (int j = 0; j < 4; j++) {
        if (f[j]) {
            int slot = run++;
            if (slot < MAXV) {
                int h = base + j;
                int ix = h / (GY * GZ), r2 = h % (GY * GZ), iy = r2 / GZ, iz = r2 % GZ;
                int cell = (iz * GY + iy) * GX + ix;
                g_m0[cell] = 1;
                g_list0[slot] = h;
                g_list0cell[slot] = cell;
            }
        }
    }
}

// ---------------- weight prep ----------------
__global__ void vfe_prep(const float* __restrict__ w1, const float* __restrict__ b1,
                         const float* __restrict__ g1, const float* __restrict__ be1,
                         const float* __restrict__ w2, const float* __restrict__ b2,
                         const float* __restrict__ g2, const float* __restrict__ be2) {
    int t = threadIdx.x; // 128
    if (t < 32) {
        float gg = g1[t];
        for (int ic = 0; ic < 5; ic++) g_vfe1t[ic * 32 + t] = w1[t * 5 + ic] * gg;
        g_vfe1b[t] = b1[t] * gg + be1[t];
    }
    {
        float gg = g2[t];
        for (int ic = 0; ic < 32; ic++) g_vfe2t[ic * 128 + t] = w2[t * 32 + ic] * gg;
        g_vfe2b[t] = b2[t] * gg + be2[t];
    }
    __shared__ float sp0[32];
    if (t < 32) sp0[t] = fmaxf(g_vfe1b[t], 0.0f);
    __syncthreads();
    float acc = g_vfe2b[t];
    for (int ic = 0; ic < 32; ic++) acc = fmaf(sp0[ic], g_vfe2t[ic * 128 + t], acc);
    g_pad[t] = fmaxf(acc, 0.0f);
}

// (O,I,KK) src -> dst[(k*I+i)*O+o] = src[o][i][k] * g[o]
__global__ void transpose_w(const float* __restrict__ src, const float* __restrict__ g,
                            float* __restrict__ dst, int O, int I, int KK) {
    int idx = blockIdx.x * blockDim.x + threadIdx.x;
    int total = O * I * KK;
    if (idx >= total) return;
    int o = idx % O;
    int rest = idx / O;
    int i = rest % I;
    int k = rest / I;
    dst[idx] = src[((size_t)o * I + i) * KK + k] * g[o];
}

__global__ void fold_bias(const float* __restrict__ b, const float* __restrict__ g,
                          const float* __restrict__ be, float* __restrict__ dst, int n) {
    int i = blockIdx.x * blockDim.x + threadIdx.x;
    if (i < n) dst[i] = b[i] * g[i] + be[i];
}

// ---------------- VFE ----------------
__global__ void __launch_bounds__(128) vfe_kernel() {
    __shared__ float sW2[32 * 128];
    __shared__ float sW1[5 * 32];
    __shared__ float sB1[32];
    __shared__ float sP[32];
    int t = threadIdx.x;
    for (int i = t; i < 32 * 128; i += 128) sW2[i] = g_vfe2t[i];
    for (int i = t; i < 160; i += 128) sW1[i] = g_vfe1t[i];
    if (t < 32) sB1[t] = g_vfe1b[t];
    float b2 = g_vfe2b[t];
    float padv = g_pad[t];
    int K = g_cntArr[0];
    __syncthreads();
    for (int v = 0; v < 8; v++) {
        int s = blockIdx.x * 8 + v;
        if (s >= K) break;
        int h = g_list0[s];
        int cell = g_list0cell[s];
        int n = g_count[h]; if (n > MAXP) n = MAXP;
        float m = (n < MAXP) ? padv : -1e30f;
        for (int j = 0; j < n; j++) {
            __syncthreads();
            if (t < 32) {
                const float* pt = g_pbuf + ((size_t)h * MAXP + j) * 5;
                float a = sB1[t];
#pragma unroll
                for (int ic = 0; ic < 5; ic++) a = fmaf(pt[ic], sW1[ic * 32 + t], a);
                sP[t] = fmaxf(a, 0.0f);
            }
            __syncthreads();
            float acc = b2;
#pragma unroll
            for (int ic = 0; ic < 32; ic++) acc = fmaf(sP[ic], sW2[ic * 128 + t], acc);
            m = fmaxf(m, fmaxf(acc, 0.0f));
        }
        g_feat0[(size_t)cell * 128 + t] = m;
    }
}

// ---------------- occupancy pooling ----------------
__global__ void pool1() {
    int idx = blockIdx.x * blockDim.x + threadIdx.x;
    if (idx >= N1) return;
    int z = idx / 2500, r = idx % 2500, y = r / 50, x = r % 50;
    bool any = false;
    for (int dz = -1; dz <= 1; dz++) { int nz = 2 * z + dz; if (nz < 0 || nz >= GZ) continue;
        for (int dy = -1; dy <= 1; dy++) { int ny = 2 * y + dy; if (ny < 0 || ny >= GY) continue;
            for (int dx = -1; dx <= 1; dx++) { int nx = 2 * x + dx; if (nx < 0 || nx >= GX) continue;
                any |= (g_m0[(nz * GY + ny) * GX + nx] != 0); } } }
    if (any) { g_m1[idx] = 1; int p = atomicAdd(&g_cntArr[1], 1); g_list1[p] = idx; }
}

__global__ void pool2() {
    int idx = blockIdx.x * blockDim.x + threadIdx.x;
    if (idx >= N2) return;
    int z = idx / P2D, r = idx % P2D, y = r / 25, x = r % 25;
    bool any = false;
    for (int dz = -1; dz <= 1; dz++) { int nz = 2 * z + dz; if (nz < 0 || nz >= 10) continue;
        for (int dy = -1; dy <= 1; dy++) { int ny = 2 * y + dy; if (ny < 0 || ny >= 50) continue;
            for (int dx = -1; dx <= 1; dx++) { int nx = 2 * x + dx; if (nx < 0 || nx >= 50) continue;
                any |= (g_m1[(nz * 50 + ny) * 50 + nx] != 0); } } }
    if (any) { g_m2[idx] = 1; int p = atomicAdd(&g_cntArr[2], 1); g_list2[p] = idx; }
}

// ---------------- sparse 3D conv (gather over active list) ----------------
template<int IC, int OC, int S, int STR, int IZ, int IY, int IX, int OZ, int OY, int OX>
__global__ void __launch_bounds__(OC) spconv(const float* __restrict__ inF,
                                             const unsigned char* __restrict__ inM,
                                             const float* __restrict__ wt,
                                             const float* __restrict__ beta,
                                             const int* __restrict__ listCell,
                                             int cntIdx,
                                             float* __restrict__ outF) {
    __shared__ float sIn[IC * (S + 1)];
    __shared__ int sNb[S];
    __shared__ int sCell[S], sCz[S], sCy[S], sCx[S];
    const int t = threadIdx.x;
    const int cnt = g_cntArr[cntIdx];
    const int base = blockIdx.x * S;
    if (base >= cnt) return;
    if (t < S) {
        int s = base + t;
        if (s < cnt) {
            int cell = listCell[s];
            sCell[t] = cell;
            sCz[t] = cell / (OY * OX);
            int r = cell % (OY * OX);
            sCy[t] = r / OX; sCx[t] = r % OX;
        } else { sCell[t] = -1; sCz[t] = -100000; sCy[t] = 0; sCx[t] = 0; }
    }
    float acc[S];
#pragma unroll
    for (int i = 0; i < S; i++) acc[i] = 0.0f;
    const float bet = beta[t];
    __syncthreads();
    for (int k = 0; k < 27; k++) {
        int kd = k / 9 - 1, kh = (k / 3) % 3 - 1, kw = k % 3 - 1;
        __syncthreads();
        if (t < S) {
            int nb = -1;
            int nz = sCz[t] * STR + kd, ny = sCy[t] * STR + kh, nx = sCx[t] * STR + kw;
            if (nz >= 0 && nz < IZ && ny >= 0 && ny < IY && nx >= 0 && nx < IX) {
                int c = (nz * IY + ny) * IX + nx;
                if (inM[c]) nb = c;
            }
            sNb[t] = nb;
        }
        __syncthreads();
        for (int i = t; i < IC * S; i += OC) {
            int s = i / IC, ic = i % IC;
            int nb = sNb[s];
            sIn[ic * (S + 1) + s] = (nb >= 0) ? inF[(size_t)nb * IC + ic] : 0.0f;
        }
        __syncthreads();
        const float* wk = wt + (size_t)k * IC * OC + t;
#pragma unroll 4
        for (int ic = 0; ic < IC; ic++) {
            float w = wk[ic * OC];
            const float* si = &sIn[ic * (S + 1)];
#pragma unroll
            for (int s = 0; s < S; s++) acc[s] = fmaf(si[s], w, acc[s]);
        }
    }
#pragma unroll
    for (int s = 0; s < S; s++) {
        int cell = sCell[s];
        if (cell >= 0) outF[(size_t)cell * OC + t] = fmaxf(acc[s] + bet, 0.0f);
    }
}

// ---------------- BEV: scatter + im2col + GEMM ----------------
__global__ void bev_scatter() {
    int idx = blockIdx.x * blockDim.x + threadIdx.x;
    if (idx >= N2 * 256) return;
    int site = idx >> 8, c = idx & 255;
    int z = site / P2D, rr = site % P2D;
    float v = g_m2[site] ? g_feat4[(size_t)site * 256 + c] : 0.0f;
    g_bevin[(size_t)(z * 256 + c) * P2D + rr] = v;
}

template<int ICH>
__global__ void im2col(const float* __restrict__ in, float* __restrict__ col) {
    int idx = blockIdx.x * blockDim.x + threadIdx.x;
    if (idx >= 9 * ICH * P2D) return;
    int p = idx % P2D;
    int r = idx / P2D;
    int ch = r % ICH, k = r / ICH;
    int ky = k / 3, kx = k % 3;
    int y = p / 25, x = p % 25;
    int sy = y + ky - 1, sx = x + kx - 1;
    float v = 0.0f;
    if (sy >= 0 && sy < 25 && sx >= 0 && sx < 25) v = in[(size_t)ch * P2D + sy * 25 + sx];
    col[idx] = v;
}

// C[oc*625+p] = relu(bias[oc] + sum_r A[r*OC+oc] * B[r*625+p])
template<int OC, int K>
__global__ void __launch_bounds__(256) gemm_bias_relu(const float* __restrict__ A,
                                                      const float* __restrict__ B,
                                                      const float* __restrict__ bias,
                                                      float* __restrict__ C) {
    __shared__ float As[8][64];
    __shared__ float Bs[8][65];
    int t = threadIdx.x;
    int tx = t % 16, ty = t / 16;
    int bx = blockIdx.x, by = blockIdx.y;
    int oc0 = by * 64, p0 = bx * 64;
    float acc[4][4];
#pragma unroll
    for (int i = 0; i < 4; i++)
#pragma unroll
        for (int j = 0; j < 4; j++) acc[i][j] = 0.0f;
    for (int k0 = 0; k0 < K; k0 += 8) {
        // load A tile: 512 elems
#pragma unroll
        for (int e = 0; e < 2; e++) {
            int li = t * 2 + e;
            int kk = li >> 6, c = li & 63;
            As[kk][c] = A[(size_t)(k0 + kk) * OC + oc0 + c];
            int pp = p0 + c;
            Bs[kk][c] = (pp < P2D) ? B[(size_t)(k0 + kk) * P2D + pp] : 0.0f;
        }
        __syncthreads();
#pragma unroll
        for (int kk = 0; kk < 8; kk++) {
            float a[4], b[4];
#pragma unroll
            for (int i = 0; i < 4; i++) a[i] = As[kk][tx * 4 + i];
#pragma unroll
            for (int j = 0; j < 4; j++) b[j] = Bs[kk][ty * 4 + j];
#pragma unroll
            for (int i = 0; i < 4; i++)
#pragma unroll
                for (int j = 0; j < 4; j++) acc[i][j] = fmaf(a[i], b[j], acc[i][j]);
        }
        __syncthreads();
    }
#pragma unroll
    for (int i = 0; i < 4; i++) {
        int oc = oc0 + tx * 4 + i;
        float bv = bias[oc];
#pragma unroll
        for (int j = 0; j < 4; j++) {
            int p = p0 + ty * 4 + j;
            if (p < P2D) C[(size_t)oc * P2D + p] = fmaxf(acc[i][j] + bv, 0.0f);
        }
    }
}

// ---------------- host ----------------
static inline void* sym(const void* s) { void* p = nullptr; cudaGetSymbolAddress(&p, s); return p; }

extern "C" void kernel_launch(void* const* d_in, const int* in_sizes, int n_in,
                              void* d_out, int out_size) {
    const float* points = (const float*)d_in[0];
    const float *vfe1_w = (const float*)d_in[1], *vfe1_b = (const float*)d_in[2],
                *vfe1_g = (const float*)d_in[3], *vfe1_be = (const float*)d_in[4];
    const float *vfe2_w = (const float*)d_in[5], *vfe2_b = (const float*)d_in[6],
                *vfe2_g = (const float*)d_in[7], *vfe2_be = (const float*)d_in[8];
    const float *sp1_w = (const float*)d_in[9],  *sp1_g = (const float*)d_in[10], *sp1_be = (const float*)d_in[11];
    const float *sp2_w = (const float*)d_in[12], *sp2_g = (const float*)d_in[13], *sp2_be = (const float*)d_in[14];
    const float *sp3_w = (const float*)d_in[15], *sp3_g = (const float*)d_in[16], *sp3_be = (const float*)d_in[17];
    const float *sp4_w = (const float*)d_in[18], *sp4_g = (const float*)d_in[19], *sp4_be = (const float*)d_in[20];
    const float *bev1_w = (const float*)d_in[21], *bev1_b = (const float*)d_in[22],
                *bev1_g = (const float*)d_in[23], *bev1_be = (const float*)d_in[24];
    const float *bev2_w = (const float*)d_in[25], *bev2_b = (const float*)d_in[26],
                *bev2_g = (const float*)d_in[27], *bev2_be = (const float*)d_in[28];

    int Npts = in_sizes[0] / 5;

    float* w1t = (float*)sym(g_w1t);  float* w2t = (float*)sym(g_w2t);
    float* w3t = (float*)sym(g_w3t);  float* w4t = (float*)sym(g_w4t);
    float* wb1t = (float*)sym(g_wb1t); float* wb2t = (float*)sym(g_wb2t);
    float* bb1 = (float*)sym(g_bb1);  float* bb2 = (float*)sym(g_bb2);
    float* f0 = (float*)sym(g_feat0); float* f1 = (float*)sym(g_feat1);
    float* f2 = (float*)sym(g_feat2); float* f3 = (float*)sym(g_feat3);
    float* f4 = (float*)sym(g_feat4);
    unsigned char* m0 = (unsigned char*)sym(g_m0);
    unsigned char* m1 = (unsigned char*)sym(g_m1);
    int* l0c = (int*)sym(g_list0cell);
    int* l1 = (int*)sym(g_list1); int* l2 = (int*)sym(g_list2);
    float* bevin = (float*)sym(g_bevin);
    float* col1 = (float*)sym(g_col1); float* col2 = (float*)sym(g_col2);
    float* bev1o = (float*)sym(g_bev1);

    zero_misc<<<(NVOX + 255) / 256, 256>>>();

    vfe_prep<<<1, 128>>>(vfe1_w, vfe1_b, vfe1_g, vfe1_be, vfe2_w, vfe2_b, vfe2_g, vfe2_be);
    transpose_w<<<(27 * 128 * 64 + 255) / 256, 256>>>(sp1_w, sp1_g, w1t, 64, 128, 27);
    transpose_w<<<(27 * 64 * 128 + 255) / 256, 256>>>(sp2_w, sp2_g, w2t, 128, 64, 27);
    transpose_w<<<(27 * 128 * 128 + 255) / 256, 256>>>(sp3_w, sp3_g, w3t, 128, 128, 27);
    transpose_w<<<(27 * 128 * 256 + 255) / 256, 256>>>(sp4_w, sp4_g, w4t, 256, 128, 27);
    transpose_w<<<(9 * 1280 * 512 + 255) / 256, 256>>>(bev1_w, bev1_g, wb1t, 512, 1280, 9);
    transpose_w<<<(9 * 512 * 256 + 255) / 256, 256>>>(bev2_w, bev2_g, wb2t, 256, 512, 9);
    fold_bias<<<2, 256>>>(bev1_b, bev1_g, bev1_be, bb1, 512);
    fold_bias<<<1, 256>>>(bev2_b, bev2_g, bev2_be, bb2, 256);

    scatter_pts<<<(Npts + 255) / 256, 256>>>(points, Npts);
    scan_p1<<<NB_SCAN, 256>>>();
    scan_p2<<<1, 32>>>();
    scan_p3<<<NB_SCAN, 256>>>();

    vfe_kernel<<<(MAXV + 7) / 8, 128>>>();

    pool1<<<(N1 + 255) / 256, 256>>>();
    pool2<<<(N2 + 255) / 256, 256>>>();

    spconv<128, 64, 16, 1, 20, 100, 100, 20, 100, 100><<<(MAXV + 15) / 16, 64>>>(
        f0, m0, w1t, sp1_be, l0c, 0, f1);
    spconv<64, 128, 16, 2, 20, 100, 100, 10, 50, 50><<<(N1 + 15) / 16, 128>>>(
        f1, m0, w2t, sp2_be, l1, 1, f2);
    spconv<128, 128, 16, 1, 10, 50, 50, 10, 50, 50><<<(N1 + 15) / 16, 128>>>(
        f2, m1, w3t, sp3_be, l1, 1, f3);
    spconv<128, 256, 16, 2, 10, 50, 50, 5, 25, 25><<<(N2 + 15) / 16, 256>>>(
        f3, m1, w4t, sp4_be, l2, 2, f4);

    bev_scatter<<<(N2 * 256 + 255) / 256, 256>>>();
    im2col<1280><<<(9 * 1280 * P2D + 255) / 256, 256>>>(bevin, col1);
    {
        dim3 g((P2D + 63) / 64, 512 / 64);
        gemm_bias_relu<512, 11520><<<g, 256>>>(wb1t, col1, bb1, bev1o);
    }
    im2col<512><<<(9 * 512 * P2D + 255) / 256, 256>>>(bev1o, col2);
    {
        dim3 g((P2D + 63) / 64, 256 / 64);
        gemm_bias_relu<256, 4608><<<g, 256>>>(wb2t, col2, bb2, (float*)d_out);
    }
}

// round 3
// speedup vs baseline: 1.1271x; 1.1271x over previous
#include <cuda_runtime.h>
#include <cuda_bf16.h>
#include <cstdint>

// ---------------- constants ----------------
static constexpr int GX = 100, GY = 100, GZ = 20;
static constexpr int NVOX = GX * GY * GZ;            // 200000
static constexpr int MAXV = 60000, MAXP = 10;
static constexpr int NB_SCAN = (NVOX + 1023) / 1024; // 196
static constexpr int N1 = 10 * 50 * 50;              // 25000
static constexpr int N2 = 5 * 25 * 25;               // 3125
static constexpr int P2D = 625;                      // 25*25

// ---------------- device scratch ----------------
__device__ int           g_count[NVOX];
__device__ float         g_pbuf[(size_t)NVOX * MAXP * 5];
__device__ unsigned char g_m0[NVOX];
__device__ unsigned char g_m1[N1];
__device__ unsigned char g_m2[N2];
__device__ int           g_list0[MAXV];
__device__ int           g_list0cell[MAXV];
__device__ int           g_list1[N1];
__device__ int           g_list2[N2];
__device__ int           g_cntArr[3];
__device__ int           g_bsum[NB_SCAN], g_boff[NB_SCAN];

__device__ float g_feat0[(size_t)NVOX * 128];
__device__ float g_feat1[(size_t)NVOX * 64];
__device__ float g_feat2[(size_t)N1 * 128];
__device__ float g_feat3[(size_t)N1 * 128];
__device__ float g_feat4[(size_t)N2 * 256];
__device__ float g_bevin[(size_t)1280 * P2D];
__device__ float g_col1[(size_t)11520 * P2D];
__device__ float g_col2[(size_t)4608 * P2D];
__device__ float g_bev1[(size_t)512 * P2D];
__device__ float g_part[(size_t)2 * 512 * P2D];      // split-K partials (640000 floats)

__device__ float g_w1t[27 * 128 * 64];
__device__ float g_w2t[27 * 64 * 128];
__device__ float g_w3t[27 * 128 * 128];
__device__ float g_w4t[27 * 128 * 256];
__device__ float g_wb1t[9 * 1280 * 512];
__device__ float g_wb2t[9 * 512 * 256];
__device__ float g_vfe1t[5 * 32], g_vfe1b[32];
__device__ float g_vfe2t[32 * 128], g_vfe2b[128];
__device__ float g_pad[128];
__device__ float g_bb1[512], g_bb2[256];

// ---------------- f32x2 helpers ----------------
__device__ __forceinline__ void fma2(unsigned long long& d, unsigned long long a, unsigned long long b) {
    asm("fma.rn.f32x2 %0, %1, %2, %0;" : "+l"(d) : "l"(a), "l"(b));
}
__device__ __forceinline__ unsigned long long dup2(float w) {
    unsigned int u = __float_as_uint(w);
    unsigned long long r;
    asm("mov.b64 %0, {%1, %1};" : "=l"(r) : "r"(u));
    return r;
}

// ---------------- zero / init ----------------
__global__ void zero_misc() {
    int i = blockIdx.x * blockDim.x + threadIdx.x;
    if (i < NVOX) { g_count[i] = 0; g_m0[i] = 0; }
    if (i < N1) g_m1[i] = 0;
    if (i < N2) g_m2[i] = 0;
    if (i < 3) g_cntArr[i] = 0;
}

// ---------------- voxelize ----------------
__global__ void scatter_pts(const float* __restrict__ pts, int N) {
    int i = blockIdx.x * blockDim.x + threadIdx.x;
    if (i >= N) return;
    const float* p = pts + (size_t)i * 5;
    float x = p[0], y = p[1], z = p[2];
    if (x == 0.0f) return;
    int ix = (int)floorf(__fdiv_rn(__fsub_rn(x, -51.2f), 1.024f));
    int iy = (int)floorf(__fdiv_rn(__fsub_rn(y, -51.2f), 1.024f));
    int iz = (int)floorf(__fdiv_rn(__fsub_rn(z, -5.0f), 0.4f));
    if (ix < 0 || ix >= GX || iy < 0 || iy >= GY || iz < 0 || iz >= GZ) return;
    int h = ix * (GY * GZ) + iy * GZ + iz;
    int r = atomicAdd(&g_count[h], 1);
    if (r < MAXP) {
        float* d = g_pbuf + ((size_t)h * MAXP + r) * 5;
        d[0] = x; d[1] = y; d[2] = z; d[3] = p[3]; d[4] = p[4];
    }
}

__global__ void scan_p1() {
    int b = blockIdx.x, t = threadIdx.x;
    int base = b * 1024 + t * 4;
    int s = 0;
#pragma unroll
    for (int j = 0; j < 4; j++) { int h = base + j; if (h < NVOX && g_count[h] != 0) s++; }
#pragma unroll
    for (int o = 16; o > 0; o >>= 1) s += __shfl_down_sync(0xffffffffu, s, o);
    __shared__ int ws[8];
    if ((t & 31) == 0) ws[t >> 5] = s;
    __syncthreads();
    if (t == 0) { int tot = 0; for (int i = 0; i < 8; i++) tot += ws[i]; g_bsum[b] = tot; }
}

__global__ void scan_p2() {
    if (threadIdx.x == 0) {
        int r = 0;
        for (int i = 0; i < NB_SCAN; i++) { g_boff[i] = r; r += g_bsum[i]; }
        g_cntArr[0] = (r < MAXV) ? r : MAXV;
    }
}

__global__ void scan_p3() {
    int b = blockIdx.x, t = threadIdx.x;
    int base = b * 1024 + t * 4;
    int f[4]; int tsum = 0;
#pragma unroll
    for (int j = 0; j < 4; j++) { int h = base + j; f[j] = (h < NVOX && g_count[h] != 0) ? 1 : 0; tsum += f[j]; }
    int lane = t & 31, wid = t >> 5;
    int incl = tsum;
#pragma unroll
    for (int o = 1; o < 32; o <<= 1) { int v = __shfl_up_sync(0xffffffffu, incl, o); if (lane >= o) incl += v; }
    __shared__ int wsum[8], woff[8];
    if (lane == 31) wsum[wid] = incl;
    __syncthreads();
    if (t == 0) { int r = 0; for (int i = 0; i < 8; i++) { woff[i] = r; r += wsum[i]; } }
    __syncthreads();
    int run = g_boff[b] + woff[wid] + (incl - tsum);
#pragma unroll
    for (int j = 0; j < 4; j++) {
        if (f[j]) {
            int slot = run++;
            if (slot < MAXV) {
                int h = base + j;
                int ix = h / (GY * GZ), r2 = h % (GY * GZ), iy = r2 / GZ, iz = r2 % GZ;
                int cell = (iz * GY + iy) * GX + ix;
                g_m0[cell] = 1;
                g_list0[slot] = h;
                g_list0cell[slot] = cell;
            }
        }
    }
}

// ---------------- weight prep ----------------
__global__ void vfe_prep(const float* __restrict__ w1, const float* __restrict__ b1,
                         const float* __restrict__ g1, const float* __restrict__ be1,
                         const float* __restrict__ w2, const float* __restrict__ b2,
                         const float* __restrict__ g2, const float* __restrict__ be2) {
    int t = threadIdx.x; // 128
    if (t < 32) {
        float gg = g1[t];
        for (int ic = 0; ic < 5; ic++) g_vfe1t[ic * 32 + t] = w1[t * 5 + ic] * gg;
        g_vfe1b[t] = b1[t] * gg + be1[t];
    }
    {
        float gg = g2[t];
        for (int ic = 0; ic < 32; ic++) g_vfe2t[ic * 128 + t] = w2[t * 32 + ic] * gg;
        g_vfe2b[t] = b2[t] * gg + be2[t];
    }
    __shared__ float sp0[32];
    if (t < 32) sp0[t] = fmaxf(g_vfe1b[t], 0.0f);
    __syncthreads();
    float acc = g_vfe2b[t];
    for (int ic = 0; ic < 32; ic++) acc = fmaf(sp0[ic], g_vfe2t[ic * 128 + t], acc);
    g_pad[t] = fmaxf(acc, 0.0f);
}

// src[(o*I+i)*KK+k]*g[o] -> dst[(k*I+i)*O+o]; reads coalesced, writes scattered
__global__ void transpose_w(const float* __restrict__ src, const float* __restrict__ g,
                            float* __restrict__ dst, int O, int I, int KK) {
    int idx = blockIdx.x * blockDim.x + threadIdx.x;
    int total = O * I * KK;
    if (idx >= total) return;
    int k = idx % KK;
    int rest = idx / KK;
    int i = rest % I;
    int o = rest / I;
    dst[((size_t)k * I + i) * O + o] = src[idx] * g[o];
}

__global__ void fold_bias(const float* __restrict__ b, const float* __restrict__ g,
                          const float* __restrict__ be, float* __restrict__ dst, int n) {
    int i = blockIdx.x * blockDim.x + threadIdx.x;
    if (i < n) dst[i] = b[i] * g[i] + be[i];
}

// ---------------- VFE ----------------
__global__ void __launch_bounds__(128) vfe_kernel() {
    __shared__ float sW2[32 * 128];
    __shared__ float sW1[5 * 32];
    __shared__ float sB1[32];
    __shared__ float sP[32];
    int t = threadIdx.x;
    for (int i = t; i < 32 * 128; i += 128) sW2[i] = g_vfe2t[i];
    for (int i = t; i < 160; i += 128) sW1[i] = g_vfe1t[i];
    if (t < 32) sB1[t] = g_vfe1b[t];
    float b2 = g_vfe2b[t];
    float padv = g_pad[t];
    int K = g_cntArr[0];
    __syncthreads();
    for (int v = 0; v < 8; v++) {
        int s = blockIdx.x * 8 + v;
        if (s >= K) break;
        int h = g_list0[s];
        int cell = g_list0cell[s];
        int n = g_count[h]; if (n > MAXP) n = MAXP;
        float m = (n < MAXP) ? padv : -1e30f;
        for (int j = 0; j < n; j++) {
            __syncthreads();
            if (t < 32) {
                const float* pt = g_pbuf + ((size_t)h * MAXP + j) * 5;
                float a = sB1[t];
#pragma unroll
                for (int ic = 0; ic < 5; ic++) a = fmaf(pt[ic], sW1[ic * 32 + t], a);
                sP[t] = fmaxf(a, 0.0f);
            }
            __syncthreads();
            float acc = b2;
#pragma unroll
            for (int ic = 0; ic < 32; ic++) acc = fmaf(sP[ic], sW2[ic * 128 + t], acc);
            m = fmaxf(m, fmaxf(acc, 0.0f));
        }
        g_feat0[(size_t)cell * 128 + t] = m;
    }
}

// ---------------- occupancy pooling ----------------
__global__ void pool1() {
    int idx = blockIdx.x * blockDim.x + threadIdx.x;
    if (idx >= N1) return;
    int z = idx / 2500, r = idx % 2500, y = r / 50, x = r % 50;
    bool any = false;
    for (int dz = -1; dz <= 1; dz++) { int nz = 2 * z + dz; if (nz < 0 || nz >= GZ) continue;
        for (int dy = -1; dy <= 1; dy++) { int ny = 2 * y + dy; if (ny < 0 || ny >= GY) continue;
            for (int dx = -1; dx <= 1; dx++) { int nx = 2 * x + dx; if (nx < 0 || nx >= GX) continue;
                any |= (g_m0[(nz * GY + ny) * GX + nx] != 0); } } }
    if (any) { g_m1[idx] = 1; int p = atomicAdd(&g_cntArr[1], 1); g_list1[p] = idx; }
}

__global__ void pool2() {
    int idx = blockIdx.x * blockDim.x + threadIdx.x;
    if (idx >= N2) return;
    int z = idx / P2D, r = idx % P2D, y = r / 25, x = r % 25;
    bool any = false;
    for (int dz = -1; dz <= 1; dz++) { int nz = 2 * z + dz; if (nz < 0 || nz >= 10) continue;
        for (int dy = -1; dy <= 1; dy++) { int ny = 2 * y + dy; if (ny < 0 || ny >= 50) continue;
            for (int dx = -1; dx <= 1; dx++) { int nx = 2 * x + dx; if (nx < 0 || nx >= 50) continue;
                any |= (g_m1[(nz * 50 + ny) * 50 + nx] != 0); } } }
    if (any) { g_m2[idx] = 1; int p = atomicAdd(&g_cntArr[2], 1); g_list2[p] = idx; }
}

// ---------------- sparse 3D conv: f32x2 over site pairs ----------------
template<int IC, int OC, int S, int STR, int IZ, int IY, int IX, int OZ, int OY, int OX>
__global__ void __launch_bounds__(OC) spconv(const float* __restrict__ inF,
                                             const unsigned char* __restrict__ inM,
                                             const float* __restrict__ wt,
                                             const float* __restrict__ beta,
                                             const int* __restrict__ listCell,
                                             int cntIdx,
                                             float* __restrict__ outF) {
    static_assert(S % 4 == 0, "");
    constexpr int PAD = S + 4;                       // rows 16B-aligned
    __shared__ __align__(16) float sIn[IC * PAD];
    __shared__ int sNb[S];
    __shared__ int sCell[S], sCz[S], sCy[S], sCx[S];
    const int t = threadIdx.x;
    const int cnt = g_cntArr[cntIdx];
    const int base = blockIdx.x * S;
    if (base >= cnt) return;
    if (t < S) {
        int s = base + t;
        if (s < cnt) {
            int cell = listCell[s];
            sCell[t] = cell;
            sCz[t] = cell / (OY * OX);
            int r = cell % (OY * OX);
            sCy[t] = r / OX; sCx[t] = r % OX;
        } else { sCell[t] = -1; sCz[t] = -100000; sCy[t] = 0; sCx[t] = 0; }
    }
    unsigned long long acc2[S / 2];
#pragma unroll
    for (int i = 0; i < S / 2; i++) acc2[i] = 0ull;
    const float bet = beta[t];
    __syncthreads();
    for (int k = 0; k < 27; k++) {
        int kd = k / 9 - 1, kh = (k / 3) % 3 - 1, kw = k % 3 - 1;
        __syncthreads();
        if (t < S) {
            int nb = -1;
            int nz = sCz[t] * STR + kd, ny = sCy[t] * STR + kh, nx = sCx[t] * STR + kw;
            if (nz >= 0 && nz < IZ && ny >= 0 && ny < IY && nx >= 0 && nx < IX) {
                int c = (nz * IY + ny) * IX + nx;
                if (inM[c]) nb = c;
            }
            sNb[t] = nb;
        }
        __syncthreads();
        // gather: i = c4*S + s  (stride-1 STS across lanes, float4 LDG)
        constexpr int NV = IC / 4;
        for (int i = t; i < NV * S; i += OC) {
            int c = i / S, s = i % S;
            int nb = sNb[s];
            float4 v = make_float4(0.f, 0.f, 0.f, 0.f);
            if (nb >= 0) v = reinterpret_cast<const float4*>(inF + (size_t)nb * IC)[c];
            float* dst = sIn + (4 * c) * PAD + s;
            dst[0] = v.x; dst[PAD] = v.y; dst[2 * PAD] = v.z; dst[3 * PAD] = v.w;
        }
        __syncthreads();
        const float* wk = wt + (size_t)k * IC * OC + t;
#pragma unroll 4
        for (int ic = 0; ic < IC; ic++) {
            unsigned long long w2 = dup2(wk[(size_t)ic * OC]);
            const ulonglong2* si4 = reinterpret_cast<const ulonglong2*>(sIn + ic * PAD);
#pragma unroll
            for (int q = 0; q < S / 4; q++) {
                ulonglong2 pr = si4[q];
                fma2(acc2[2 * q], pr.x, w2);
                fma2(acc2[2 * q + 1], pr.y, w2);
            }
        }
    }
#pragma unroll
    for (int sp = 0; sp < S / 2; sp++) {
        unsigned long long v = acc2[sp];
        float lo = __uint_as_float((unsigned)v);
        float hi = __uint_as_float((unsigned)(v >> 32));
        int c0 = sCell[2 * sp], c1 = sCell[2 * sp + 1];
        if (c0 >= 0) outF[(size_t)c0 * OC + t] = fmaxf(lo + bet, 0.0f);
        if (c1 >= 0) outF[(size_t)c1 * OC + t] = fmaxf(hi + bet, 0.0f);
    }
}

// ---------------- BEV: scatter + im2col + split-K GEMM ----------------
__global__ void bev_scatter() {
    int idx = blockIdx.x * blockDim.x + threadIdx.x;
    if (idx >= N2 * 256) return;
    int site = idx >> 8, c = idx & 255;
    int z = site / P2D, rr = site % P2D;
    float v = g_m2[site] ? g_feat4[(size_t)site * 256 + c] : 0.0f;
    g_bevin[(size_t)(z * 256 + c) * P2D + rr] = v;
}

template<int ICH>
__global__ void im2col(const float* __restrict__ in, float* __restrict__ col) {
    int idx = blockIdx.x * blockDim.x + threadIdx.x;
    if (idx >= 9 * ICH * P2D) return;
    int p = idx % P2D;
    int r = idx / P2D;
    int ch = r % ICH, k = r / ICH;
    int ky = k / 3, kx = k % 3;
    int y = p / 25, x = p % 25;
    int sy = y + ky - 1, sx = x + kx - 1;
    float v = 0.0f;
    if (sy >= 0 && sy < 25 && sx >= 0 && sx < 25) v = in[(size_t)ch * P2D + sy * 25 + sx];
    col[idx] = v;
}

// split-K GEMM: partial[kz][oc][p] += A[r][oc] * B[r][p], f32x2 over p pairs
template<int OC, int K, int SPLIT>
__global__ void __launch_bounds__(256) gemm_f2(const float* __restrict__ A,
                                               const float* __restrict__ B) {
    __shared__ __align__(16) unsigned long long As2[8][64];
    __shared__ __align__(16) float Bs[8][68];
    const int t = threadIdx.x, tx = t & 15, ty = t >> 4;
    const int p0 = blockIdx.x * 64, oc0 = blockIdx.y * 64;
    const int kz = blockIdx.z;
    constexpr int KC = K / SPLIT;
    unsigned long long acc2[4][2] = {};
    const int kbeg = kz * KC;
    for (int k0 = kbeg; k0 < kbeg + KC; k0 += 8) {
#pragma unroll
        for (int e = 0; e < 2; e++) {
            int li = e * 256 + t;
            int kk = li >> 6, c = li & 63;
            float a = A[(size_t)(k0 + kk) * OC + oc0 + c];
            As2[kk][c] = dup2(a);
            int pp = p0 + c;
            Bs[kk][c] = (pp < P2D) ? B[(size_t)(k0 + kk) * P2D + pp] : 0.0f;
        }
        __syncthreads();
#pragma unroll
        for (int kk = 0; kk < 8; kk++) {
            const ulonglong2* ap = reinterpret_cast<const ulonglong2*>(&As2[kk][tx * 4]);
            ulonglong2 aA = ap[0], aB = ap[1];
            const unsigned long long* bp = reinterpret_cast<const unsigned long long*>(&Bs[kk][ty * 4]);
            unsigned long long b0 = bp[0], b1 = bp[1];
            fma2(acc2[0][0], aA.x, b0); fma2(acc2[0][1], aA.x, b1);
            fma2(acc2[1][0], aA.y, b0); fma2(acc2[1][1], aA.y, b1);
            fma2(acc2[2][0], aB.x, b0); fma2(acc2[2][1], aB.x, b1);
            fma2(acc2[3][0], aB.y, b0); fma2(acc2[3][1], aB.y, b1);
        }
        __syncthreads();
    }
#pragma unroll
    for (int i = 0; i < 4; i++) {
        int oc = oc0 + tx * 4 + i;
        float* cp = g_part + ((size_t)kz * OC + oc) * P2D;
#pragma unroll
        for (int j = 0; j < 2; j++) {
            unsigned long long v = acc2[i][j];
            int p = p0 + ty * 4 + 2 * j;
            if (p < P2D) cp[p] = __uint_as_float((unsigned)v);
            if (p + 1 < P2D) cp[p + 1] = __uint_as_float((unsigned)(v >> 32));
        }
    }
}

template<int OC, int SPLIT>
__global__ void combine_bias_relu(const float* __restrict__ bias, float* __restrict__ out) {
    int idx = blockIdx.x * blockDim.x + threadIdx.x;
    if (idx >= OC * P2D) return;
    int oc = idx / P2D;
    float s = bias[oc];
#pragma unroll
    for (int z = 0; z < SPLIT; z++) s += g_part[(size_t)z * OC * P2D + idx];
    out[idx] = fmaxf(s, 0.0f);
}

// ---------------- host ----------------
static inline void* sym(const void* s) { void* p = nullptr; cudaGetSymbolAddress(&p, s); return p; }

extern "C" void kernel_launch(void* const* d_in, const int* in_sizes, int n_in,
                              void* d_out, int out_size) {
    const float* points = (const float*)d_in[0];
    const float *vfe1_w = (const float*)d_in[1], *vfe1_b = (const float*)d_in[2],
                *vfe1_g = (const float*)d_in[3], *vfe1_be = (const float*)d_in[4];
    const float *vfe2_w = (const float*)d_in[5], *vfe2_b = (const float*)d_in[6],
                *vfe2_g = (const float*)d_in[7], *vfe2_be = (const float*)d_in[8];
    const float *sp1_w = (const float*)d_in[9],  *sp1_g = (const float*)d_in[10], *sp1_be = (const float*)d_in[11];
    const float *sp2_w = (const float*)d_in[12], *sp2_g = (const float*)d_in[13], *sp2_be = (const float*)d_in[14];
    const float *sp3_w = (const float*)d_in[15], *sp3_g = (const float*)d_in[16], *sp3_be = (const float*)d_in[17];
    const float *sp4_w = (const float*)d_in[18], *sp4_g = (const float*)d_in[19], *sp4_be = (const float*)d_in[20];
    const float *bev1_w = (const float*)d_in[21], *bev1_b = (const float*)d_in[22],
                *bev1_g = (const float*)d_in[23], *bev1_be = (const float*)d_in[24];
    const float *bev2_w = (const float*)d_in[25], *bev2_b = (const float*)d_in[26],
                *bev2_g = (const float*)d_in[27], *bev2_be = (const float*)d_in[28];

    int Npts = in_sizes[0] / 5;

    float* w1t = (float*)sym(g_w1t);  float* w2t = (float*)sym(g_w2t);
    float* w3t = (float*)sym(g_w3t);  float* w4t = (float*)sym(g_w4t);
    float* wb1t = (float*)sym(g_wb1t); float* wb2t = (float*)sym(g_wb2t);
    float* bb1 = (float*)sym(g_bb1);  float* bb2 = (float*)sym(g_bb2);
    float* f0 = (float*)sym(g_feat0); float* f1 = (float*)sym(g_feat1);
    float* f2 = (float*)sym(g_feat2); float* f3 = (float*)sym(g_feat3);
    float* f4 = (float*)sym(g_feat4);
    unsigned char* m0 = (unsigned char*)sym(g_m0);
    unsigned char* m1 = (unsigned char*)sym(g_m1);
    int* l0c = (int*)sym(g_list0cell);
    int* l1 = (int*)sym(g_list1); int* l2 = (int*)sym(g_list2);
    float* bevin = (float*)sym(g_bevin);
    float* col1 = (float*)sym(g_col1); float* col2 = (float*)sym(g_col2);
    float* bev1o = (float*)sym(g_bev1);

    zero_misc<<<(NVOX + 255) / 256, 256>>>();

    vfe_prep<<<1, 128>>>(vfe1_w, vfe1_b, vfe1_g, vfe1_be, vfe2_w, vfe2_b, vfe2_g, vfe2_be);
    transpose_w<<<(27 * 128 * 64 + 255) / 256, 256>>>(sp1_w, sp1_g, w1t, 64, 128, 27);
    transpose_w<<<(27 * 64 * 128 + 255) / 256, 256>>>(sp2_w, sp2_g, w2t, 128, 64, 27);
    transpose_w<<<(27 * 128 * 128 + 255) / 256, 256>>>(sp3_w, sp3_g, w3t, 128, 128, 27);
    transpose_w<<<(27 * 128 * 256 + 255) / 256, 256>>>(sp4_w, sp4_g, w4t, 256, 128, 27);
    transpose_w<<<(9 * 1280 * 512 + 255) / 256, 256>>>(bev1_w, bev1_g, wb1t, 512, 1280, 9);
    transpose_w<<<(9 * 512 * 256 + 255) / 256, 256>>>(bev2_w, bev2_g, wb2t, 256, 512, 9);
    fold_bias<<<2, 256>>>(bev1_b, bev1_g, bev1_be, bb1, 512);
    fold_bias<<<1, 256>>>(bev2_b, bev2_g, bev2_be, bb2, 256);

    scatter_pts<<<(Npts + 255) / 256, 256>>>(points, Npts);
    scan_p1<<<NB_SCAN, 256>>>();
    scan_p2<<<1, 32>>>();
    scan_p3<<<NB_SCAN, 256>>>();

    vfe_kernel<<<(MAXV + 7) / 8, 128>>>();

    pool1<<<(N1 + 255) / 256, 256>>>();
    pool2<<<(N2 + 255) / 256, 256>>>();

    spconv<128, 64, 32, 1, 20, 100, 100, 20, 100, 100><<<(MAXV + 31) / 32, 64>>>(
        f0, m0, w1t, sp1_be, l0c, 0, f1);
    spconv<64, 128, 32, 2, 20, 100, 100, 10, 50, 50><<<(N1 + 31) / 32, 128>>>(
        f1, m0, w2t, sp2_be, l1, 1, f2);
    spconv<128, 128, 32, 1, 10, 50, 50, 10, 50, 50><<<(N1 + 31) / 32, 128>>>(
        f2, m1, w3t, sp3_be, l1, 1, f3);
    spconv<128, 256, 16, 2, 10, 50, 50, 5, 25, 25><<<(N2 + 15) / 16, 256>>>(
        f3, m1, w4t, sp4_be, l2, 2, f4);

    bev_scatter<<<(N2 * 256 + 255) / 256, 256>>>();
    im2col<1280><<<(9 * 1280 * P2D + 255) / 256, 256>>>(bevin, col1);
    {
        dim3 g((P2D + 63) / 64, 512 / 64, 2);
        gemm_f2<512, 11520, 2><<<g, 256>>>(wb1t, col1);
        combine_bias_relu<512, 2><<<(512 * P2D + 255) / 256, 256>>>(bb1, bev1o);
    }
    im2col<512><<<(9 * 512 * P2D + 255) / 256, 256>>>(bev1o, col2);
    {
        dim3 g((P2D + 63) / 64, 256 / 64, 4);
        gemm_f2<256, 4608, 4><<<g, 256>>>(wb2t, col2);
        combine_bias_relu<256, 4><<<(256 * P2D + 255) / 256, 256>>>(bb2, (float*)d_out);
    }
}

// round 4
// speedup vs baseline: 1.1770x; 1.0442x over previous
#include <cuda_runtime.h>
#include <cuda_bf16.h>
#include <cstdint>

// ---------------- constants ----------------
static constexpr int GX = 100, GY = 100, GZ = 20;
static constexpr int NVOX = GX * GY * GZ;            // 200000
static constexpr int MAXV = 60000, MAXP = 10;
static constexpr int NCHUNK = (NVOX + 1023) / 1024;  // 196
static constexpr int N1 = 10 * 50 * 50;              // 25000
static constexpr int N2 = 5 * 25 * 25;               // 3125
static constexpr int P2D = 625;                      // 25*25

// ---------------- device scratch ----------------
__device__ int           g_count[NVOX];
__device__ float         g_pbuf[(size_t)NVOX * MAXP * 5];
__device__ unsigned char g_m0[NVOX];
__device__ unsigned char g_m1[N1];
__device__ unsigned char g_m2[N2];
__device__ int           g_list0[MAXV];
__device__ int           g_list0cell[MAXV];
__device__ int           g_list1[N1];
__device__ int           g_list2[N2];
__device__ int           g_cntArr[3];

__device__ float g_feat0[(size_t)NVOX * 128];
__device__ float g_feat1[(size_t)NVOX * 64];
__device__ float g_feat2[(size_t)N1 * 128];
__device__ float g_feat3[(size_t)N1 * 128];
__device__ float g_feat4[(size_t)N2 * 256];
__device__ float g_col1[(size_t)11520 * P2D];
__device__ float g_col2[(size_t)4608 * P2D];
__device__ float g_bev1[(size_t)512 * P2D];
__device__ float g_part[(size_t)4 * 512 * P2D];

__device__ float g_w1t[27 * 128 * 64];
__device__ float g_w2t[27 * 64 * 128];
__device__ float g_w3t[27 * 128 * 128];
__device__ float g_w4t[27 * 128 * 256];
__device__ float g_wb1t[9 * 1280 * 512];
__device__ float g_wb2t[9 * 512 * 256];
__device__ float g_vfe1t[5 * 32], g_vfe1b[32];
__device__ float g_vfe2t[32 * 128], g_vfe2b[128];
__device__ float g_bb1[512], g_bb2[256];

// ---------------- f32x2 helpers ----------------
__device__ __forceinline__ void fma2(unsigned long long& d, unsigned long long a, unsigned long long b) {
    asm("fma.rn.f32x2 %0, %1, %2, %0;" : "+l"(d) : "l"(a), "l"(b));
}
__device__ __forceinline__ unsigned long long dup2(float w) {
    unsigned int u = __float_as_uint(w);
    unsigned long long r;
    asm("mov.b64 %0, {%1, %1};" : "=l"(r) : "r"(u));
    return r;
}

// ---------------- zero / init ----------------
__global__ void zero_misc() {
    int i = blockIdx.x * blockDim.x + threadIdx.x;
    if (i < NVOX) { g_count[i] = 0; g_m0[i] = 0; }
    if (i < N1) g_m1[i] = 0;
    if (i < N2) g_m2[i] = 0;
    if (i < 3) g_cntArr[i] = 0;
}

// ---------------- all weight prep in ONE kernel ----------------
__device__ __forceinline__ void tr_one(const float* __restrict__ src, const float* __restrict__ g,
                                       float* __restrict__ dst, int idx, int O, int I, int KK) {
    int o = idx % O;
    int rest = idx / O;
    int i = rest % I;
    int k = rest / I;
    dst[idx] = src[((size_t)o * I + i) * KK + k] * g[o];
}

__global__ void prep_all(
    const float* __restrict__ sp1_w, const float* __restrict__ sp1_g,
    const float* __restrict__ sp2_w, const float* __restrict__ sp2_g,
    const float* __restrict__ sp3_w, const float* __restrict__ sp3_g,
    const float* __restrict__ sp4_w, const float* __restrict__ sp4_g,
    const float* __restrict__ bev1_w, const float* __restrict__ bev1_g,
    const float* __restrict__ bev2_w, const float* __restrict__ bev2_g,
    const float* __restrict__ bev1_b, const float* __restrict__ bev1_be,
    const float* __restrict__ bev2_b, const float* __restrict__ bev2_be,
    const float* __restrict__ v1w, const float* __restrict__ v1b,
    const float* __restrict__ v1g, const float* __restrict__ v1be,
    const float* __restrict__ v2w, const float* __restrict__ v2b,
    const float* __restrict__ v2g, const float* __restrict__ v2be)
{
    int idx = blockIdx.x * blockDim.x + threadIdx.x;
    const int n0 = 27 * 128 * 64, n1 = 27 * 64 * 128, n2 = 27 * 128 * 128, n3 = 27 * 128 * 256;
    const int n4 = 9 * 1280 * 512, n5 = 9 * 512 * 256;
    if (idx < n0) { tr_one(sp1_w, sp1_g, g_w1t, idx, 64, 128, 27); return; } idx -= n0;
    if (idx < n1) { tr_one(sp2_w, sp2_g, g_w2t, idx, 128, 64, 27); return; } idx -= n1;
    if (idx < n2) { tr_one(sp3_w, sp3_g, g_w3t, idx, 128, 128, 27); return; } idx -= n2;
    if (idx < n3) { tr_one(sp4_w, sp4_g, g_w4t, idx, 256, 128, 27); return; } idx -= n3;
    if (idx < n4) { tr_one(bev1_w, bev1_g, g_wb1t, idx, 512, 1280, 9); return; } idx -= n4;
    if (idx < n5) { tr_one(bev2_w, bev2_g, g_wb2t, idx, 256, 512, 9); return; } idx -= n5;
    if (idx < 512) { g_bb1[idx] = bev1_b[idx] * bev1_g[idx] + bev1_be[idx]; return; } idx -= 512;
    if (idx < 256) { g_bb2[idx] = bev2_b[idx] * bev2_g[idx] + bev2_be[idx]; return; } idx -= 256;
    if (idx < 160) { int o = idx % 32, ic = idx / 32; g_vfe1t[idx] = v1w[o * 5 + ic] * v1g[o]; return; } idx -= 160;
    if (idx < 32) { g_vfe1b[idx] = v1b[idx] * v1g[idx] + v1be[idx]; return; } idx -= 32;
    if (idx < 4096) { int o = idx % 128, ic = idx / 128; g_vfe2t[idx] = v2w[o * 32 + ic] * v2g[o]; return; } idx -= 4096;
    if (idx < 128) { g_vfe2b[idx] = v2b[idx] * v2g[idx] + v2be[idx]; return; }
}
static constexpr int PREP_TOTAL = 27*128*64 + 27*64*128 + 27*128*128 + 27*128*256
                                + 9*1280*512 + 9*512*256 + 512 + 256 + 160 + 32 + 4096 + 128;

// ---------------- voxelize ----------------
__global__ void scatter_pts(const float* __restrict__ pts, int N) {
    int i = blockIdx.x * blockDim.x + threadIdx.x;
    if (i >= N) return;
    const float* p = pts + (size_t)i * 5;
    float x = p[0], y = p[1], z = p[2];
    if (x == 0.0f) return;
    int ix = (int)floorf(__fdiv_rn(__fsub_rn(x, -51.2f), 1.024f));
    int iy = (int)floorf(__fdiv_rn(__fsub_rn(y, -51.2f), 1.024f));
    int iz = (int)floorf(__fdiv_rn(__fsub_rn(z, -5.0f), 0.4f));
    if (ix < 0 || ix >= GX || iy < 0 || iy >= GY || iz < 0 || iz >= GZ) return;
    int h = ix * (GY * GZ) + iy * GZ + iz;
    int r = atomicAdd(&g_count[h], 1);
    if (r < MAXP) {
        float* d = g_pbuf + ((size_t)h * MAXP + r) * 5;
        d[0] = x; d[1] = y; d[2] = z; d[3] = p[3]; d[4] = p[4];
    }
}

// single-block fused scan: slot = rank of occupied hash (hash order), capped at MAXV
__global__ void __launch_bounds__(1024) scan_fused() {
    __shared__ int wS[32];
    __shared__ int sBase, sTot;
    int t = threadIdx.x, lane = t & 31, wid = t >> 5;
    if (t == 0) sBase = 0;
    __syncthreads();
    for (int chunk = 0; chunk < NCHUNK; chunk++) {
        int h = chunk * 1024 + t;
        int occ = (h < NVOX) && (g_count[h] != 0);
        unsigned bal = __ballot_sync(0xffffffffu, occ);
        int wpre = __popc(bal & ((1u << lane) - 1u));
        if (lane == 0) wS[wid] = __popc(bal);
        __syncthreads();
        if (t < 32) {
            int v = wS[t]; int incl = v;
#pragma unroll
            for (int o = 1; o < 32; o <<= 1) { int u = __shfl_up_sync(0xffffffffu, incl, o); if (lane >= o) incl += u; }
            wS[t] = incl - v;
            if (t == 31) sTot = incl;
        }
        __syncthreads();
        if (occ) {
            int slot = sBase + wS[wid] + wpre;
            if (slot < MAXV) {
                int ix = h / (GY * GZ), r2 = h % (GY * GZ), iy = r2 / GZ, iz = r2 % GZ;
                int cell = (iz * GY + iy) * GX + ix;
                g_m0[cell] = 1;
                g_list0[slot] = h;
                g_list0cell[slot] = cell;
            }
        }
        __syncthreads();
        if (t == 0) sBase += sTot;
        __syncthreads();
    }
    if (t == 0) { int r = sBase; g_cntArr[0] = (r < MAXV) ? r : MAXV; }
}

// ---------------- VFE (pad vector computed in-kernel) ----------------
__global__ void __launch_bounds__(128) vfe_kernel() {
    __shared__ float sW2[32 * 128];
    __shared__ float sW1[5 * 32];
    __shared__ float sB1[32];
    __shared__ float sP[32];
    __shared__ float sp0[32];
    int t = threadIdx.x;
    for (int i = t; i < 32 * 128; i += 128) sW2[i] = g_vfe2t[i];
    for (int i = t; i < 160; i += 128) sW1[i] = g_vfe1t[i];
    if (t < 32) { sB1[t] = g_vfe1b[t]; }
    float b2 = g_vfe2b[t];
    int K = g_cntArr[0];
    __syncthreads();
    if (t < 32) sp0[t] = fmaxf(sB1[t], 0.0f);
    __syncthreads();
    float padv = b2;
#pragma unroll
    for (int ic = 0; ic < 32; ic++) padv = fmaf(sp0[ic], sW2[ic * 128 + t], padv);
    padv = fmaxf(padv, 0.0f);
    for (int v = 0; v < 8; v++) {
        int s = blockIdx.x * 8 + v;
        if (s >= K) break;
        int h = g_list0[s];
        int cell = g_list0cell[s];
        int n = g_count[h]; if (n > MAXP) n = MAXP;
        float m = (n < MAXP) ? padv : -1e30f;
        for (int j = 0; j < n; j++) {
            __syncthreads();
            if (t < 32) {
                const float* pt = g_pbuf + ((size_t)h * MAXP + j) * 5;
                float a = sB1[t];
#pragma unroll
                for (int ic = 0; ic < 5; ic++) a = fmaf(pt[ic], sW1[ic * 32 + t], a);
                sP[t] = fmaxf(a, 0.0f);
            }
            __syncthreads();
            float acc = b2;
#pragma unroll
            for (int ic = 0; ic < 32; ic++) acc = fmaf(sP[ic], sW2[ic * 128 + t], acc);
            m = fmaxf(m, fmaxf(acc, 0.0f));
        }
        g_feat0[(size_t)cell * 128 + t] = m;
    }
}

// ---------------- occupancy pooling ----------------
__global__ void pool1() {
    int idx = blockIdx.x * blockDim.x + threadIdx.x;
    if (idx >= N1) return;
    int z = idx / 2500, r = idx % 2500, y = r / 50, x = r % 50;
    bool any = false;
    for (int dz = -1; dz <= 1; dz++) { int nz = 2 * z + dz; if (nz < 0 || nz >= GZ) continue;
        for (int dy = -1; dy <= 1; dy++) { int ny = 2 * y + dy; if (ny < 0 || ny >= GY) continue;
            for (int dx = -1; dx <= 1; dx++) { int nx = 2 * x + dx; if (nx < 0 || nx >= GX) continue;
                any |= (g_m0[(nz * GY + ny) * GX + nx] != 0); } } }
    if (any) { g_m1[idx] = 1; int p = atomicAdd(&g_cntArr[1], 1); g_list1[p] = idx; }
}

__global__ void pool2() {
    int idx = blockIdx.x * blockDim.x + threadIdx.x;
    if (idx >= N2) return;
    int z = idx / P2D, r = idx % P2D, y = r / 25, x = r % 25;
    bool any = false;
    for (int dz = -1; dz <= 1; dz++) { int nz = 2 * z + dz; if (nz < 0 || nz >= 10) continue;
        for (int dy = -1; dy <= 1; dy++) { int ny = 2 * y + dy; if (ny < 0 || ny >= 50) continue;
            for (int dx = -1; dx <= 1; dx++) { int nx = 2 * x + dx; if (nx < 0 || nx >= 50) continue;
                any |= (g_m1[(nz * 50 + ny) * 50 + nx] != 0); } } }
    if (any) { g_m2[idx] = 1; int p = atomicAdd(&g_cntArr[2], 1); g_list2[p] = idx; }
}

// ---------------- sparse 3D conv: pipelined gather + f32x2 ----------------
template<int IC, int OC, int G, int S, int STR, int IZ, int IY, int IX, int OZ, int OY, int OX>
__global__ void __launch_bounds__(OC * G) spconv(const float* __restrict__ inF,
                                                 const unsigned char* __restrict__ inM,
                                                 const float* __restrict__ wt,
                                                 const float* __restrict__ beta,
                                                 const int* __restrict__ listCell,
                                                 int cntIdx,
                                                 float* __restrict__ outF) {
    constexpr int T = OC * G;
    constexpr int PAD = S + 4;
    constexpr int NV = IC / 4;
    constexpr int LPT = NV * S / T;   // float4 loads per thread
    constexpr int SG = S / G;
    static_assert(SG % 4 == 0, "");
    __shared__ __align__(16) float sIn[2][IC * PAD];
    __shared__ int sNb[27][S];
    __shared__ int sCell[S], sCz[S], sCy[S], sCx[S];
    const int t = threadIdx.x;
    const int oc = t % OC;
    const int grp = t / OC;
    const int cnt = g_cntArr[cntIdx];
    const int base = blockIdx.x * S;
    if (base >= cnt) return;
    if (t < S) {
        int s = base + t;
        if (s < cnt) {
            int cell = listCell[s];
            sCell[t] = cell;
            sCz[t] = cell / (OY * OX);
            int r = cell % (OY * OX);
            sCy[t] = r / OX; sCx[t] = r % OX;
        } else { sCell[t] = -1; sCz[t] = -100000; sCy[t] = 0; sCx[t] = 0; }
    }
    __syncthreads();
    for (int i = t; i < 27 * S; i += T) {
        int k = i / S, s = i % S;
        int kd = k / 9 - 1, kh = (k / 3) % 3 - 1, kw = k % 3 - 1;
        int nb = -1;
        int nz = sCz[s] * STR + kd, ny = sCy[s] * STR + kh, nx = sCx[s] * STR + kw;
        if (nz >= 0 && nz < IZ && ny >= 0 && ny < IY && nx >= 0 && nx < IX) {
            int c = (nz * IY + ny) * IX + nx;
            if (inM[c]) nb = c;
        }
        sNb[k][s] = nb;
    }
    __syncthreads();
    float4 st[LPT];
#pragma unroll
    for (int l = 0; l < LPT; l++) {
        int i = l * T + t; int c = i / S, s = i % S;
        int nb = sNb[0][s];
        st[l] = (nb >= 0) ? reinterpret_cast<const float4*>(inF + (size_t)nb * IC)[c]
                          : make_float4(0.f, 0.f, 0.f, 0.f);
    }
#pragma unroll
    for (int l = 0; l < LPT; l++) {
        int i = l * T + t; int c = i / S, s = i % S;
        float* d = &sIn[0][(4 * c) * PAD + s];
        d[0] = st[l].x; d[PAD] = st[l].y; d[2 * PAD] = st[l].z; d[3 * PAD] = st[l].w;
    }
    __syncthreads();
    unsigned long long acc2[SG / 2];
#pragma unroll
    for (int i = 0; i < SG / 2; i++) acc2[i] = 0ull;
    const float bet = beta[oc];
    for (int k = 0; k < 27; k++) {
        int cur = k & 1;
        if (k + 1 < 27) {
#pragma unroll
            for (int l = 0; l < LPT; l++) {
                int i = l * T + t; int c = i / S, s = i % S;
                int nb = sNb[k + 1][s];
                st[l] = (nb >= 0) ? reinterpret_cast<const float4*>(inF + (size_t)nb * IC)[c]
                                  : make_float4(0.f, 0.f, 0.f, 0.f);
            }
        }
        const float* wk = wt + (size_t)k * IC * OC + oc;
#pragma unroll 4
        for (int ic = 0; ic < IC; ic++) {
            unsigned long long w2 = dup2(wk[(size_t)ic * OC]);
            const ulonglong2* si = reinterpret_cast<const ulonglong2*>(&sIn[cur][ic * PAD + grp * SG]);
#pragma unroll
            for (int q = 0; q < SG / 4; q++) {
                ulonglong2 pr = si[q];
                fma2(acc2[2 * q], pr.x, w2);
                fma2(acc2[2 * q + 1], pr.y, w2);
            }
        }
        if (k + 1 < 27) {
#pragma unroll
            for (int l = 0; l < LPT; l++) {
                int i = l * T + t; int c = i / S, s = i % S;
                float* d = &sIn[cur ^ 1][(4 * c) * PAD + s];
                d[0] = st[l].x; d[PAD] = st[l].y; d[2 * PAD] = st[l].z; d[3 * PAD] = st[l].w;
            }
        }
        __syncthreads();
    }
#pragma unroll
    for (int j = 0; j < SG / 2; j++) {
        unsigned long long v = acc2[j];
        float lo = __uint_as_float((unsigned)v);
        float hi = __uint_as_float((unsigned)(v >> 32));
        int s0 = grp * SG + 2 * j;
        int c0 = sCell[s0], c1 = sCell[s0 + 1];
        if (c0 >= 0) outF[(size_t)c0 * OC + oc] = fmaxf(lo + bet, 0.0f);
        if (c1 >= 0) outF[(size_t)c1 * OC + oc] = fmaxf(hi + bet, 0.0f);
    }
}

// ---------------- BEV ----------------
// fused scatter+im2col for layer 1 (reads sparse feat4 directly)
__global__ void im2col1(float* __restrict__ col) {
    int idx = blockIdx.x * blockDim.x + threadIdx.x;
    if (idx >= 9 * 1280 * P2D) return;
    int p = idx % P2D;
    int r = idx / P2D;
    int ch = r % 1280, k = r / 1280;
    int ky = k / 3, kx = k % 3;
    int y = p / 25, x = p % 25;
    int sy = y + ky - 1, sx = x + kx - 1;
    float v = 0.0f;
    if (sy >= 0 && sy < 25 && sx >= 0 && sx < 25) {
        int z = ch >> 8, c = ch & 255;
        int site = z * P2D + sy * 25 + sx;
        if (g_m2[site]) v = g_feat4[(size_t)site * 256 + c];
    }
    col[idx] = v;
}

template<int ICH>
__global__ void im2col(const float* __restrict__ in, float* __restrict__ col) {
    int idx = blockIdx.x * blockDim.x + threadIdx.x;
    if (idx >= 9 * ICH * P2D) return;
    int p = idx % P2D;
    int r = idx / P2D;
    int ch = r % ICH, k = r / ICH;
    int ky = k / 3, kx = k % 3;
    int y = p / 25, x = p % 25;
    int sy = y + ky - 1, sx = x + kx - 1;
    float v = 0.0f;
    if (sy >= 0 && sy < 25 && sx >= 0 && sx < 25) v = in[(size_t)ch * P2D + sy * 25 + sx];
    col[idx] = v;
}

// split-K GEMM, register-staged double buffering, f32x2
template<int OC, int K, int SPLIT>
__global__ void __launch_bounds__(256) gemm_f2(const float* __restrict__ A,
                                               const float* __restrict__ B) {
    __shared__ __align__(16) unsigned long long As2[2][8][64];
    __shared__ __align__(16) float Bs[2][8][68];
    const int t = threadIdx.x, tx = t & 15, ty = t >> 4;
    const int p0 = blockIdx.x * 64, oc0 = blockIdx.y * 64;
    constexpr int KC = K / SPLIT;
    const int kbeg = blockIdx.z * KC, kend = kbeg + KC;
    float ra[2], rb[2];
#pragma unroll
    for (int e = 0; e < 2; e++) {
        int li = e * 256 + t, kk = li >> 6, c = li & 63;
        ra[e] = A[(size_t)(kbeg + kk) * OC + oc0 + c];
        int pp = p0 + c;
        rb[e] = (pp < P2D) ? B[(size_t)(kbeg + kk) * P2D + pp] : 0.0f;
    }
    unsigned long long acc2[4][2] = {};
    int buf = 0;
    for (int k0 = kbeg; k0 < kend; k0 += 8) {
#pragma unroll
        for (int e = 0; e < 2; e++) {
            int li = e * 256 + t, kk = li >> 6, c = li & 63;
            As2[buf][kk][c] = dup2(ra[e]);
            Bs[buf][kk][c] = rb[e];
        }
        __syncthreads();
        if (k0 + 8 < kend) {
#pragma unroll
            for (int e = 0; e < 2; e++) {
                int li = e * 256 + t, kk = li >> 6, c = li & 63;
                ra[e] = A[(size_t)(k0 + 8 + kk) * OC + oc0 + c];
                int pp = p0 + c;
                rb[e] = (pp < P2D) ? B[(size_t)(k0 + 8 + kk) * P2D + pp] : 0.0f;
            }
        }
#pragma unroll
        for (int kk = 0; kk < 8; kk++) {
            const ulonglong2* ap = reinterpret_cast<const ulonglong2*>(&As2[buf][kk][tx * 4]);
            ulonglong2 aA = ap[0], aB = ap[1];
            const unsigned long long* bp = reinterpret_cast<const unsigned long long*>(&Bs[buf][kk][ty * 4]);
            unsigned long long b0 = bp[0], b1 = bp[1];
            fma2(acc2[0][0], aA.x, b0); fma2(acc2[0][1], aA.x, b1);
            fma2(acc2[1][0], aA.y, b0); fma2(acc2[1][1], aA.y, b1);
            fma2(acc2[2][0], aB.x, b0); fma2(acc2[2][1], aB.x, b1);
            fma2(acc2[3][0], aB.y, b0); fma2(acc2[3][1], aB.y, b1);
        }
        buf ^= 1;
    }
#pragma unroll
    for (int i = 0; i < 4; i++) {
        int oc = oc0 + tx * 4 + i;
        float* cp = g_part + ((size_t)blockIdx.z * OC + oc) * P2D;
#pragma unroll
        for (int j = 0; j < 2; j++) {
            unsigned long long v = acc2[i][j];
            int p = p0 + ty * 4 + 2 * j;
            if (p < P2D) cp[p] = __uint_as_float((unsigned)v);
            if (p + 1 < P2D) cp[p + 1] = __uint_as_float((unsigned)(v >> 32));
        }
    }
}

template<int OC, int SPLIT>
__global__ void combine_bias_relu(const float* __restrict__ bias, float* __restrict__ out) {
    int idx = blockIdx.x * blockDim.x + threadIdx.x;
    if (idx >= OC * P2D) return;
    int oc = idx / P2D;
    float s = bias[oc];
#pragma unroll
    for (int z = 0; z < SPLIT; z++) s += g_part[(size_t)z * OC * P2D + idx];
    out[idx] = fmaxf(s, 0.0f);
}

// ---------------- host ----------------
static inline void* sym(const void* s) { void* p = nullptr; cudaGetSymbolAddress(&p, s); return p; }

extern "C" void kernel_launch(void* const* d_in, const int* in_sizes, int n_in,
                              void* d_out, int out_size) {
    const float* points = (const float*)d_in[0];
    const float *vfe1_w = (const float*)d_in[1], *vfe1_b = (const float*)d_in[2],
                *vfe1_g = (const float*)d_in[3], *vfe1_be = (const float*)d_in[4];
    const float *vfe2_w = (const float*)d_in[5], *vfe2_b = (const float*)d_in[6],
                *vfe2_g = (const float*)d_in[7], *vfe2_be = (const float*)d_in[8];
    const float *sp1_w = (const float*)d_in[9],  *sp1_g = (const float*)d_in[10], *sp1_be = (const float*)d_in[11];
    const float *sp2_w = (const float*)d_in[12], *sp2_g = (const float*)d_in[13], *sp2_be = (const float*)d_in[14];
    const float *sp3_w = (const float*)d_in[15], *sp3_g = (const float*)d_in[16], *sp3_be = (const float*)d_in[17];
    const float *sp4_w = (const float*)d_in[18], *sp4_g = (const float*)d_in[19], *sp4_be = (const float*)d_in[20];
    const float *bev1_w = (const float*)d_in[21], *bev1_b = (const float*)d_in[22],
                *bev1_g = (const float*)d_in[23], *bev1_be = (const float*)d_in[24];
    const float *bev2_w = (const float*)d_in[25], *bev2_b = (const float*)d_in[26],
                *bev2_g = (const float*)d_in[27], *bev2_be = (const float*)d_in[28];

    int Npts = in_sizes[0] / 5;

    float* w1t = (float*)sym(g_w1t);  float* w2t = (float*)sym(g_w2t);
    float* w3t = (float*)sym(g_w3t);  float* w4t = (float*)sym(g_w4t);
    float* wb1t = (float*)sym(g_wb1t); float* wb2t = (float*)sym(g_wb2t);
    float* bb1 = (float*)sym(g_bb1);  float* bb2 = (float*)sym(g_bb2);
    float* f0 = (float*)sym(g_feat0); float* f1 = (float*)sym(g_feat1);
    float* f2 = (float*)sym(g_feat2); float* f3 = (float*)sym(g_feat3);
    unsigned char* m0 = (unsigned char*)sym(g_m0);
    unsigned char* m1 = (unsigned char*)sym(g_m1);
    int* l0c = (int*)sym(g_list0cell);
    int* l1 = (int*)sym(g_list1); int* l2 = (int*)sym(g_list2);
    float* col1 = (float*)sym(g_col1); float* col2 = (float*)sym(g_col2);
    float* bev1o = (float*)sym(g_bev1);

    // launch index:
    zero_misc<<<(NVOX + 255) / 256, 256>>>();                                   // 0
    prep_all<<<(PREP_TOTAL + 255) / 256, 256>>>(                                 // 1
        sp1_w, sp1_g, sp2_w, sp2_g, sp3_w, sp3_g, sp4_w, sp4_g,
        bev1_w, bev1_g, bev2_w, bev2_g, bev1_b, bev1_be, bev2_b, bev2_be,
        vfe1_w, vfe1_b, vfe1_g, vfe1_be, vfe2_w, vfe2_b, vfe2_g, vfe2_be);
    scatter_pts<<<(Npts + 255) / 256, 256>>>(points, Npts);                      // 2
    scan_fused<<<1, 1024>>>();                                                   // 3
    vfe_kernel<<<(MAXV + 7) / 8, 128>>>();                                       // 4
    spconv<128, 64, 2, 32, 1, 20, 100, 100, 20, 100, 100><<<(MAXV + 31) / 32, 128>>>(
        f0, m0, w1t, sp1_be, l0c, 0, f1);                                        // 5  <-- profiled
    pool1<<<(N1 + 255) / 256, 256>>>();                                          // 6
    spconv<64, 128, 2, 32, 2, 20, 100, 100, 10, 50, 50><<<(N1 + 31) / 32, 256>>>(
        f1, m0, w2t, sp2_be, l1, 1, f2);                                         // 7
    spconv<128, 128, 2, 32, 1, 10, 50, 50, 10, 50, 50><<<(N1 + 31) / 32, 256>>>(
        f2, m1, w3t, sp3_be, l1, 1, f3);                                         // 8
    pool2<<<(N2 + 255) / 256, 256>>>();                                          // 9
    spconv<128, 256, 1, 16, 2, 10, 50, 50, 5, 25, 25><<<(N2 + 15) / 16, 256>>>(
        f3, m1, w4t, sp4_be, l2, 2, (float*)sym(g_feat4));                       // 10
    im2col1<<<(9 * 1280 * P2D + 255) / 256, 256>>>(col1);                        // 11
    {
        dim3 g((P2D + 63) / 64, 512 / 64, 4);
        gemm_f2<512, 11520, 4><<<g, 256>>>(wb1t, col1);                          // 12
        combine_bias_relu<512, 4><<<(512 * P2D + 255) / 256, 256>>>(bb1, bev1o); // 13
    }
    im2col<512><<<(9 * 512 * P2D + 255) / 256, 256>>>(bev1o, col2);              // 14
    {
        dim3 g((P2D + 63) / 64, 256 / 64, 4);
        gemm_f2<256, 4608, 4><<<g, 256>>>(wb2t, col2);                           // 15
        combine_bias_relu<256, 4><<<(256 * P2D + 255) / 256, 256>>>(bb2, (float*)d_out); // 16
    }
}

// round 5
// speedup vs baseline: 1.2098x; 1.0279x over previous
#include <cuda_runtime.h>
#include <cuda_bf16.h>
#include <cstdint>

// ---------------- constants ----------------
static constexpr int GX = 100, GY = 100, GZ = 20;
static constexpr int NVOX = GX * GY * GZ;            // 200000
static constexpr int MAXV = 60000, MAXP = 10;
static constexpr int N1 = 10 * 50 * 50;              // 25000
static constexpr int N2 = 5 * 25 * 25;               // 3125
static constexpr int P2D = 625;                      // 25*25

// ---------------- device scratch (static zero-init; final kernel re-zeroes) ----
__device__ int           g_count[NVOX];
__device__ float         g_pbuf[(size_t)NVOX * MAXP * 5];
__device__ unsigned char g_m0[NVOX];
__device__ unsigned char g_m1[N1];
__device__ unsigned char g_m2[N2];
__device__ int           g_list0[MAXV];
__device__ int           g_list0cell[MAXV];
__device__ int           g_list1[N1];
__device__ int           g_list2[N2];
__device__ int           g_cntArr[3];

__device__ float g_feat0[(size_t)NVOX * 128];
__device__ float g_feat1[(size_t)NVOX * 64];
__device__ float g_feat2[(size_t)N1 * 128];
__device__ float g_feat3[(size_t)N1 * 128];
__device__ float g_feat4[(size_t)N2 * 256];
__device__ float g_col1[(size_t)11520 * P2D];
__device__ float g_col2[(size_t)4608 * P2D];
__device__ float g_bev1[(size_t)512 * P2D];
__device__ float g_part[(size_t)4 * 512 * P2D];

__device__ float g_w1t[27 * 128 * 64];
__device__ float g_w2t[27 * 64 * 128];
__device__ float g_w3t[27 * 128 * 128];
__device__ float g_w4t[27 * 128 * 256];
__device__ float g_wb1t[9 * 1280 * 512];
__device__ float g_wb2t[9 * 512 * 256];
__device__ float g_vfe1t[5 * 32], g_vfe1b[32];
__device__ float g_vfe2t[32 * 128], g_vfe2b[128];
__device__ float g_bb1[512], g_bb2[256];

// ---------------- f32x2 helpers ----------------
__device__ __forceinline__ void fma2(unsigned long long& d, unsigned long long a, unsigned long long b) {
    asm("fma.rn.f32x2 %0, %1, %2, %0;" : "+l"(d) : "l"(a), "l"(b));
}
__device__ __forceinline__ unsigned long long dup2(float w) {
    unsigned int u = __float_as_uint(w);
    unsigned long long r;
    asm("mov.b64 %0, {%1, %1};" : "=l"(r) : "r"(u));
    return r;
}

// ---------------- fused scatter + weight prep ----------------
static constexpr int SCAT_BLOCKS = (250000 + 255) / 256;   // blocks for point scatter (input N<=250000)
__device__ __forceinline__ void tr_one(const float* __restrict__ src, const float* __restrict__ g,
                                       float* __restrict__ dst, int idx, int O, int I, int KK) {
    int o = idx % O;
    int rest = idx / O;
    int i = rest % I;
    int k = rest / I;
    dst[idx] = src[((size_t)o * I + i) * KK + k] * g[o];
}

static constexpr int PREP_TOTAL = 27*128*64 + 27*64*128 + 27*128*128 + 27*128*256
                                + 9*1280*512 + 9*512*256 + 512 + 256 + 160 + 32 + 4096 + 128;
static constexpr int PREP_BLOCKS = (PREP_TOTAL + 255) / 256;

__global__ void __launch_bounds__(256) scatter_prep(
    const float* __restrict__ pts, int N,
    const float* __restrict__ sp1_w, const float* __restrict__ sp1_g,
    const float* __restrict__ sp2_w, const float* __restrict__ sp2_g,
    const float* __restrict__ sp3_w, const float* __restrict__ sp3_g,
    const float* __restrict__ sp4_w, const float* __restrict__ sp4_g,
    const float* __restrict__ bev1_w, const float* __restrict__ bev1_g,
    const float* __restrict__ bev2_w, const float* __restrict__ bev2_g,
    const float* __restrict__ bev1_b, const float* __restrict__ bev1_be,
    const float* __restrict__ bev2_b, const float* __restrict__ bev2_be,
    const float* __restrict__ v1w, const float* __restrict__ v1b,
    const float* __restrict__ v1g, const float* __restrict__ v1be,
    const float* __restrict__ v2w, const float* __restrict__ v2b,
    const float* __restrict__ v2g, const float* __restrict__ v2be)
{
    if (blockIdx.x < SCAT_BLOCKS) {
        int i = blockIdx.x * 256 + threadIdx.x;
        if (i >= N) return;
        const float* p = pts + (size_t)i * 5;
        float x = p[0], y = p[1], z = p[2];
        if (x == 0.0f) return;
        int ix = (int)floorf(__fdiv_rn(__fsub_rn(x, -51.2f), 1.024f));
        int iy = (int)floorf(__fdiv_rn(__fsub_rn(y, -51.2f), 1.024f));
        int iz = (int)floorf(__fdiv_rn(__fsub_rn(z, -5.0f), 0.4f));
        if (ix < 0 || ix >= GX || iy < 0 || iy >= GY || iz < 0 || iz >= GZ) return;
        int h = ix * (GY * GZ) + iy * GZ + iz;
        int r = atomicAdd(&g_count[h], 1);
        if (r < MAXP) {
            float* d = g_pbuf + ((size_t)h * MAXP + r) * 5;
            d[0] = x; d[1] = y; d[2] = z; d[3] = p[3]; d[4] = p[4];
        }
        return;
    }
    int idx = (blockIdx.x - SCAT_BLOCKS) * 256 + threadIdx.x;
    const int n0 = 27 * 128 * 64, n1c = 27 * 64 * 128, n2c = 27 * 128 * 128, n3 = 27 * 128 * 256;
    const int n4 = 9 * 1280 * 512, n5 = 9 * 512 * 256;
    if (idx < n0) { tr_one(sp1_w, sp1_g, g_w1t, idx, 64, 128, 27); return; } idx -= n0;
    if (idx < n1c) { tr_one(sp2_w, sp2_g, g_w2t, idx, 128, 64, 27); return; } idx -= n1c;
    if (idx < n2c) { tr_one(sp3_w, sp3_g, g_w3t, idx, 128, 128, 27); return; } idx -= n2c;
    if (idx < n3) { tr_one(sp4_w, sp4_g, g_w4t, idx, 256, 128, 27); return; } idx -= n3;
    if (idx < n4) { tr_one(bev1_w, bev1_g, g_wb1t, idx, 512, 1280, 9); return; } idx -= n4;
    if (idx < n5) { tr_one(bev2_w, bev2_g, g_wb2t, idx, 256, 512, 9); return; } idx -= n5;
    if (idx < 512) { g_bb1[idx] = bev1_b[idx] * bev1_g[idx] + bev1_be[idx]; return; } idx -= 512;
    if (idx < 256) { g_bb2[idx] = bev2_b[idx] * bev2_g[idx] + bev2_be[idx]; return; } idx -= 256;
    if (idx < 160) { int o = idx % 32, ic = idx / 32; g_vfe1t[idx] = v1w[o * 5 + ic] * v1g[o]; return; } idx -= 160;
    if (idx < 32) { g_vfe1b[idx] = v1b[idx] * v1g[idx] + v1be[idx]; return; } idx -= 32;
    if (idx < 4096) { int o = idx % 128, ic = idx / 128; g_vfe2t[idx] = v2w[o * 32 + ic] * v2g[o]; return; } idx -= 4096;
    if (idx < 128) { g_vfe2b[idx] = v2b[idx] * v2g[idx] + v2be[idx]; return; }
}

// ---------------- scan: single block, int4 + ballot, ~2 barriers/iter -------
__global__ void __launch_bounds__(1024) scan_opt() {
    __shared__ int wS[32];
    __shared__ int sBase, sTot;
    const int t = threadIdx.x, lane = t & 31, wid = t >> 5;
    if (t == 0) sBase = 0;
    __syncthreads();
    const int NIT = (NVOX + 4095) / 4096;   // 49
    int4 cur;
    {
        int base = t * 4;
        cur = (base + 3 < NVOX) ? *reinterpret_cast<const int4*>(&g_count[base])
                                : make_int4(0, 0, 0, 0);
    }
    for (int it = 0; it < NIT; it++) {
        int base = it * 4096 + t * 4;
        int4 nxt = make_int4(0, 0, 0, 0);
        if (it + 1 < NIT) {
            int nb = (it + 1) * 4096 + t * 4;
            if (nb + 3 < NVOX) nxt = *reinterpret_cast<const int4*>(&g_count[nb]);
            else {
                if (nb + 0 < NVOX) nxt.x = g_count[nb + 0];
                if (nb + 1 < NVOX) nxt.y = g_count[nb + 1];
                if (nb + 2 < NVOX) nxt.z = g_count[nb + 2];
                if (nb + 3 < NVOX) nxt.w = g_count[nb + 3];
            }
        }
        int f0 = (base + 0 < NVOX) && cur.x, f1 = (base + 1 < NVOX) && cur.y;
        int f2 = (base + 2 < NVOX) && cur.z, f3 = (base + 3 < NVOX) && cur.w;
        int tc = f0 + f1 + f2 + f3;
        int incl = tc;
#pragma unroll
        for (int o = 1; o < 32; o <<= 1) { int u = __shfl_up_sync(0xffffffffu, incl, o); if (lane >= o) incl += u; }
        if (lane == 31) wS[wid] = incl;
        __syncthreads();
        if (t < 32) {
            int v = wS[t]; int wi = v;
#pragma unroll
            for (int o = 1; o < 32; o <<= 1) { int u = __shfl_up_sync(0xffffffffu, wi, o); if (lane >= o) wi += u; }
            wS[t] = wi - v;
            if (t == 31) sTot = wi;
        }
        __syncthreads();
        int pos = sBase + wS[wid] + (incl - tc);
        int fl[4] = {f0, f1, f2, f3};
#pragma unroll
        for (int j = 0; j < 4; j++) {
            if (fl[j]) {
                int slot = pos++;
                if (slot < MAXV) {
                    int h = base + j;
                    int ix = h / (GY * GZ), r2 = h % (GY * GZ), iy = r2 / GZ, iz = r2 % GZ;
                    int cell = (iz * GY + iy) * GX + ix;
                    g_m0[cell] = 1;
                    g_list0[slot] = h;
                    g_list0cell[slot] = cell;
                }
            }
        }
        __syncthreads();
        if (t == 0) sBase += sTot;
        cur = nxt;
        __syncthreads();
    }
    if (t == 0) { int r = sBase; g_cntArr[0] = (r < MAXV) ? r : MAXV; }
}

// ---------------- VFE: warp-per-voxel, no block barriers in mainloop --------
__global__ void __launch_bounds__(256) vfe_warp() {
    __shared__ float4 sW2v[32][32];   // [ic][lane] -> oc {lane, 32+lane, 64+lane, 96+lane}
    __shared__ float sW1[5 * 32];
    __shared__ float sB1[32];
    __shared__ float4 sB2v[32];
    __shared__ float sP[8][32];
    const int t = threadIdx.x, lane = t & 31, w = t >> 5;
    for (int i = t; i < 32 * 32; i += 256) {
        int ic = i >> 5, l = i & 31;
        sW2v[ic][l] = make_float4(g_vfe2t[ic * 128 + l], g_vfe2t[ic * 128 + 32 + l],
                                  g_vfe2t[ic * 128 + 64 + l], g_vfe2t[ic * 128 + 96 + l]);
    }
    if (t < 160) sW1[t] = g_vfe1t[t];
    if (t < 32) {
        sB1[t] = g_vfe1b[t];
        sB2v[t] = make_float4(g_vfe2b[t], g_vfe2b[32 + t], g_vfe2b[64 + t], g_vfe2b[96 + t]);
    }
    __syncthreads();
    const int K = g_cntArr[0];
    const int s = blockIdx.x * 8 + w;
    if (s >= K) return;
    const int h = g_list0[s];
    const int cell = g_list0cell[s];
    int n = g_count[h]; if (n > MAXP) n = MAXP;
    const float4 b2 = sB2v[lane];
    float4 m;
    {   // padding-row feature (zero point): p = relu(b1)
        sP[w][lane] = fmaxf(sB1[lane], 0.0f);
        __syncwarp();
        float4 a = b2;
#pragma unroll
        for (int ic = 0; ic < 32; ic++) {
            float pv = sP[w][ic];
            float4 wv = sW2v[ic][lane];
            a.x = fmaf(pv, wv.x, a.x); a.y = fmaf(pv, wv.y, a.y);
            a.z = fmaf(pv, wv.z, a.z); a.w = fmaf(pv, wv.w, a.w);
        }
        if (n < MAXP) {
            m = make_float4(fmaxf(a.x, 0.f), fmaxf(a.y, 0.f), fmaxf(a.z, 0.f), fmaxf(a.w, 0.f));
        } else {
            m = make_float4(-1e30f, -1e30f, -1e30f, -1e30f);
        }
    }
    for (int j = 0; j < n; j++) {
        const float* pt = g_pbuf + ((size_t)h * MAXP + j) * 5;
        float a1 = sB1[lane];
#pragma unroll
        for (int c = 0; c < 5; c++) a1 = fmaf(pt[c], sW1[c * 32 + lane], a1);
        __syncwarp();
        sP[w][lane] = fmaxf(a1, 0.0f);
        __syncwarp();
        float4 a = b2;
#pragma unroll
        for (int ic = 0; ic < 32; ic++) {
            float pv = sP[w][ic];
            float4 wv = sW2v[ic][lane];
            a.x = fmaf(pv, wv.x, a.x); a.y = fmaf(pv, wv.y, a.y);
            a.z = fmaf(pv, wv.z, a.z); a.w = fmaf(pv, wv.w, a.w);
        }
        m.x = fmaxf(m.x, fmaxf(a.x, 0.f)); m.y = fmaxf(m.y, fmaxf(a.y, 0.f));
        m.z = fmaxf(m.z, fmaxf(a.z, 0.f)); m.w = fmaxf(m.w, fmaxf(a.w, 0.f));
    }
    float* o = g_feat0 + (size_t)cell * 128;
    o[lane] = m.x; o[32 + lane] = m.y; o[64 + lane] = m.z; o[96 + lane] = m.w;
}

// ---------------- occupancy pooling ----------------
__global__ void pool1() {
    int idx = blockIdx.x * blockDim.x + threadIdx.x;
    if (idx >= N1) return;
    int z = idx / 2500, r = idx % 2500, y = r / 50, x = r % 50;
    bool any = false;
    for (int dz = -1; dz <= 1; dz++) { int nz = 2 * z + dz; if (nz < 0 || nz >= GZ) continue;
        for (int dy = -1; dy <= 1; dy++) { int ny = 2 * y + dy; if (ny < 0 || ny >= GY) continue;
            for (int dx = -1; dx <= 1; dx++) { int nx = 2 * x + dx; if (nx < 0 || nx >= GX) continue;
                any |= (g_m0[(nz * GY + ny) * GX + nx] != 0); } } }
    if (any) { g_m1[idx] = 1; int p = atomicAdd(&g_cntArr[1], 1); g_list1[p] = idx; }
}

__global__ void pool2() {
    int idx = blockIdx.x * blockDim.x + threadIdx.x;
    if (idx >= N2) return;
    int z = idx / P2D, r = idx % P2D, y = r / 25, x = r % 25;
    bool any = false;
    for (int dz = -1; dz <= 1; dz++) { int nz = 2 * z + dz; if (nz < 0 || nz >= 10) continue;
        for (int dy = -1; dy <= 1; dy++) { int ny = 2 * y + dy; if (ny < 0 || ny >= 50) continue;
            for (int dx = -1; dx <= 1; dx++) { int nx = 2 * x + dx; if (nx < 0 || nx >= 50) continue;
                any |= (g_m1[(nz * 50 + ny) * 50 + nx] != 0); } } }
    if (any) { g_m2[idx] = 1; int p = atomicAdd(&g_cntArr[2], 1); g_list2[p] = idx; }
}

// ---------------- sparse 3D conv: pipelined gather + f32x2 ----------------
template<int IC, int OC, int G, int S, int STR, int IZ, int IY, int IX, int OZ, int OY, int OX>
__global__ void __launch_bounds__(OC * G) spconv(const float* __restrict__ inF,
                                                 const unsigned char* __restrict__ inM,
                                                 const float* __restrict__ wt,
                                                 const float* __restrict__ beta,
                                                 const int* __restrict__ listCell,
                                                 int cntIdx,
                                                 float* __restrict__ outF) {
    constexpr int T = OC * G;
    constexpr int PAD = S + 4;
    constexpr int NV = IC / 4;
    constexpr int LPT = NV * S / T;
    constexpr int SG = S / G;
    static_assert(SG % 4 == 0, "");
    static_assert((NV * S) % T == 0, "");
    __shared__ __align__(16) float sIn[2][IC * PAD];
    __shared__ int sNb[27][S];
    __shared__ int sCell[S], sCz[S], sCy[S], sCx[S];
    const int t = threadIdx.x;
    const int oc = t % OC;
    const int grp = t / OC;
    const int cnt = g_cntArr[cntIdx];
    const int base = blockIdx.x * S;
    if (base >= cnt) return;
    if (t < S) {
        int s = base + t;
        if (s < cnt) {
            int cell = listCell[s];
            sCell[t] = cell;
            sCz[t] = cell / (OY * OX);
            int r = cell % (OY * OX);
            sCy[t] = r / OX; sCx[t] = r % OX;
        } else { sCell[t] = -1; sCz[t] = -100000; sCy[t] = 0; sCx[t] = 0; }
    }
    __syncthreads();
    for (int i = t; i < 27 * S; i += T) {
        int k = i / S, s = i % S;
        int kd = k / 9 - 1, kh = (k / 3) % 3 - 1, kw = k % 3 - 1;
        int nb = -1;
        int nz = sCz[s] * STR + kd, ny = sCy[s] * STR + kh, nx = sCx[s] * STR + kw;
        if (nz >= 0 && nz < IZ && ny >= 0 && ny < IY && nx >= 0 && nx < IX) {
            int c = (nz * IY + ny) * IX + nx;
            if (inM[c]) nb = c;
        }
        sNb[k][s] = nb;
    }
    __syncthreads();
    float4 st[LPT];
#pragma unroll
    for (int l = 0; l < LPT; l++) {
        int i = l * T + t; int c = i / S, s = i % S;
        int nb = sNb[0][s];
        st[l] = (nb >= 0) ? reinterpret_cast<const float4*>(inF + (size_t)nb * IC)[c]
                          : make_float4(0.f, 0.f, 0.f, 0.f);
    }
#pragma unroll
    for (int l = 0; l < LPT; l++) {
        int i = l * T + t; int c = i / S, s = i % S;
        float* d = &sIn[0][(4 * c) * PAD + s];
        d[0] = st[l].x; d[PAD] = st[l].y; d[2 * PAD] = st[l].z; d[3 * PAD] = st[l].w;
    }
    __syncthreads();
    unsigned long long acc2[SG / 2];
#pragma unroll
    for (int i = 0; i < SG / 2; i++) acc2[i] = 0ull;
    const float bet = beta[oc];
    for (int k = 0; k < 27; k++) {
        int cur = k & 1;
        if (k + 1 < 27) {
#pragma unroll
            for (int l = 0; l < LPT; l++) {
                int i = l * T + t; int c = i / S, s = i % S;
                int nb = sNb[k + 1][s];
                st[l] = (nb >= 0) ? reinterpret_cast<const float4*>(inF + (size_t)nb * IC)[c]
                                  : make_float4(0.f, 0.f, 0.f, 0.f);
            }
        }
        const float* wk = wt + (size_t)k * IC * OC + oc;
#pragma unroll 4
        for (int ic = 0; ic < IC; ic++) {
            unsigned long long w2 = dup2(wk[(size_t)ic * OC]);
            const ulonglong2* si = reinterpret_cast<const ulonglong2*>(&sIn[cur][ic * PAD + grp * SG]);
#pragma unroll
            for (int q = 0; q < SG / 4; q++) {
                ulonglong2 pr = si[q];
                fma2(acc2[2 * q], pr.x, w2);
                fma2(acc2[2 * q + 1], pr.y, w2);
            }
        }
        if (k + 1 < 27) {
#pragma unroll
            for (int l = 0; l < LPT; l++) {
                int i = l * T + t; int c = i / S, s = i % S;
                float* d = &sIn[cur ^ 1][(4 * c) * PAD + s];
                d[0] = st[l].x; d[PAD] = st[l].y; d[2 * PAD] = st[l].z; d[3 * PAD] = st[l].w;
            }
        }
        __syncthreads();
    }
#pragma unroll
    for (int j = 0; j < SG / 2; j++) {
        unsigned long long v = acc2[j];
        float lo = __uint_as_float((unsigned)v);
        float hi = __uint_as_float((unsigned)(v >> 32));
        int s0 = grp * SG + 2 * j;
        int c0 = sCell[s0], c1 = sCell[s0 + 1];
        if (c0 >= 0) outF[(size_t)c0 * OC + oc] = fmaxf(lo + bet, 0.0f);
        if (c1 >= 0) outF[(size_t)c1 * OC + oc] = fmaxf(hi + bet, 0.0f);
    }
}

// ---------------- BEV ----------------
__global__ void im2col1(float* __restrict__ col) {
    int idx = blockIdx.x * blockDim.x + threadIdx.x;
    if (idx >= 9 * 1280 * P2D) return;
    int p = idx % P2D;
    int r = idx / P2D;
    int ch = r % 1280, k = r / 1280;
    int ky = k / 3, kx = k % 3;
    int y = p / 25, x = p % 25;
    int sy = y + ky - 1, sx = x + kx - 1;
    float v = 0.0f;
    if (sy >= 0 && sy < 25 && sx >= 0 && sx < 25) {
        int z = ch >> 8, c = ch & 255;
        int site = z * P2D + sy * 25 + sx;
        if (g_m2[site]) v = g_feat4[(size_t)site * 256 + c];
    }
    col[idx] = v;
}

template<int ICH>
__global__ void im2col(const float* __restrict__ in, float* __restrict__ col) {
    int idx = blockIdx.x * blockDim.x + threadIdx.x;
    if (idx >= 9 * ICH * P2D) return;
    int p = idx % P2D;
    int r = idx / P2D;
    int ch = r % ICH, k = r / ICH;
    int ky = k / 3, kx = k % 3;
    int y = p / 25, x = p % 25;
    int sy = y + ky - 1, sx = x + kx - 1;
    float v = 0.0f;
    if (sy >= 0 && sy < 25 && sx >= 0 && sx < 25) v = in[(size_t)ch * P2D + sy * 25 + sx];
    col[idx] = v;
}

// split-K GEMM, register-staged double buffering, f32x2
template<int OC, int K, int SPLIT>
__global__ void __launch_bounds__(256) gemm_f2(const float* __restrict__ A,
                                               const float* __restrict__ B) {
    __shared__ __align__(16) unsigned long long As2[2][8][64];
    __shared__ __align__(16) float Bs[2][8][68];
    const int t = threadIdx.x, tx = t & 15, ty = t >> 4;
    const int p0 = blockIdx.x * 64, oc0 = blockIdx.y * 64;
    constexpr int KC = K / SPLIT;
    const int kbeg = blockIdx.z * KC, kend = kbeg + KC;
    float ra[2], rb[2];
#pragma unroll
    for (int e = 0; e < 2; e++) {
        int li = e * 256 + t, kk = li >> 6, c = li & 63;
        ra[e] = A[(size_t)(kbeg + kk) * OC + oc0 + c];
        int pp = p0 + c;
        rb[e] = (pp < P2D) ? B[(size_t)(kbeg + kk) * P2D + pp] : 0.0f;
    }
    unsigned long long acc2[4][2] = {};
    int buf = 0;
    for (int k0 = kbeg; k0 < kend; k0 += 8) {
#pragma unroll
        for (int e = 0; e < 2; e++) {
            int li = e * 256 + t, kk = li >> 6, c = li & 63;
            As2[buf][kk][c] = dup2(ra[e]);
            Bs[buf][kk][c] = rb[e];
        }
        __syncthreads();
        if (k0 + 8 < kend) {
#pragma unroll
            for (int e = 0; e < 2; e++) {
                int li = e * 256 + t, kk = li >> 6, c = li & 63;
                ra[e] = A[(size_t)(k0 + 8 + kk) * OC + oc0 + c];
                int pp = p0 + c;
                rb[e] = (pp < P2D) ? B[(size_t)(k0 + 8 + kk) * P2D + pp] : 0.0f;
            }
        }
#pragma unroll
        for (int kk = 0; kk < 8; kk++) {
            const ulonglong2* ap = reinterpret_cast<const ulonglong2*>(&As2[buf][kk][tx * 4]);
            ulonglong2 aA = ap[0], aB = ap[1];
            const unsigned long long* bp = reinterpret_cast<const unsigned long long*>(&Bs[buf][kk][ty * 4]);
            unsigned long long b0 = bp[0], b1 = bp[1];
            fma2(acc2[0][0], aA.x, b0); fma2(acc2[0][1], aA.x, b1);
            fma2(acc2[1][0], aA.y, b0); fma2(acc2[1][1], aA.y, b1);
            fma2(acc2[2][0], aB.x, b0); fma2(acc2[2][1], aB.x, b1);
            fma2(acc2[3][0], aB.y, b0); fma2(acc2[3][1], aB.y, b1);
        }
        buf ^= 1;
    }
#pragma unroll
    for (int i = 0; i < 4; i++) {
        int oc = oc0 + tx * 4 + i;
        float* cp = g_part + ((size_t)blockIdx.z * OC + oc) * P2D;
#pragma unroll
        for (int j = 0; j < 2; j++) {
            unsigned long long v = acc2[i][j];
            int p = p0 + ty * 4 + 2 * j;
            if (p < P2D) cp[p] = __uint_as_float((unsigned)v);
            if (p + 1 < P2D) cp[p + 1] = __uint_as_float((unsigned)(v >> 32));
        }
    }
}

template<int OC, int SPLIT>
__global__ void combine_bias_relu(const float* __restrict__ bias, float* __restrict__ out) {
    int idx = blockIdx.x * blockDim.x + threadIdx.x;
    if (idx >= OC * P2D) return;
    int oc = idx / P2D;
    float s = bias[oc];
#pragma unroll
    for (int z = 0; z < SPLIT; z++) s += g_part[(size_t)z * OC * P2D + idx];
    out[idx] = fmaxf(s, 0.0f);
}

// final: combine2 (+bias relu -> d_out) AND re-zero all state for next call
static constexpr int COMB2_BLOCKS = (256 * P2D + 255) / 256;     // 625
static constexpr int ZC0 = NVOX;          // g_count ints
static constexpr int ZC1 = NVOX / 4;      // g_m0 as ints
static constexpr int ZC2 = N1 / 4;        // g_m1 as ints (25000/4 = 6250)
static constexpr int ZC3 = N2;            // g_m2 bytes
static constexpr int ZTOT = ZC0 + ZC1 + ZC2 + ZC3 + 3;
static constexpr int ZBLK = (ZTOT + 255) / 256;

__global__ void final_combine_zero(const float* __restrict__ bias, float* __restrict__ out) {
    if (blockIdx.x < COMB2_BLOCKS) {
        int idx = blockIdx.x * 256 + threadIdx.x;
        if (idx >= 256 * P2D) return;
        int oc = idx / P2D;
        float s = bias[oc];
#pragma unroll
        for (int z = 0; z < 4; z++) s += g_part[(size_t)z * 256 * P2D + idx];
        out[idx] = fmaxf(s, 0.0f);
        return;
    }
    int idx = (blockIdx.x - COMB2_BLOCKS) * 256 + threadIdx.x;
    if (idx < ZC0) { g_count[idx] = 0; return; } idx -= ZC0;
    if (idx < ZC1) { reinterpret_cast<int*>(g_m0)[idx] = 0; return; } idx -= ZC1;
    if (idx < ZC2) { reinterpret_cast<int*>(g_m1)[idx] = 0; return; } idx -= ZC2;
    if (idx < ZC3) { g_m2[idx] = 0; return; } idx -= ZC3;
    if (idx < 3) { g_cntArr[idx] = 0; return; }
}

// ---------------- host ----------------
static inline void* sym(const void* s) { void* p = nullptr; cudaGetSymbolAddress(&p, s); return p; }

extern "C" void kernel_launch(void* const* d_in, const int* in_sizes, int n_in,
                              void* d_out, int out_size) {
    const float* points = (const float*)d_in[0];
    const float *vfe1_w = (const float*)d_in[1], *vfe1_b = (const float*)d_in[2],
                *vfe1_g = (const float*)d_in[3], *vfe1_be = (const float*)d_in[4];
    const float *vfe2_w = (const float*)d_in[5], *vfe2_b = (const float*)d_in[6],
                *vfe2_g = (const float*)d_in[7], *vfe2_be = (const float*)d_in[8];
    const float *sp1_w = (const float*)d_in[9],  *sp1_g = (const float*)d_in[10], *sp1_be = (const float*)d_in[11];
    const float *sp2_w = (const float*)d_in[12], *sp2_g = (const float*)d_in[13], *sp2_be = (const float*)d_in[14];
    const float *sp3_w = (const float*)d_in[15], *sp3_g = (const float*)d_in[16], *sp3_be = (const float*)d_in[17];
    const float *sp4_w = (const float*)d_in[18], *sp4_g = (const float*)d_in[19], *sp4_be = (const float*)d_in[20];
    const float *bev1_w = (const float*)d_in[21], *bev1_b = (const float*)d_in[22],
                *bev1_g = (const float*)d_in[23], *bev1_be = (const float*)d_in[24];
    const float *bev2_w = (const float*)d_in[25], *bev2_b = (const float*)d_in[26],
                *bev2_g = (const float*)d_in[27], *bev2_be = (const float*)d_in[28];

    int Npts = in_sizes[0] / 5;

    float* w1t = (float*)sym(g_w1t);  float* w2t = (float*)sym(g_w2t);
    float* w3t = (float*)sym(g_w3t);  float* w4t = (float*)sym(g_w4t);
    float* wb1t = (float*)sym(g_wb1t); float* wb2t = (float*)sym(g_wb2t);
    float* bb1 = (float*)sym(g_bb1);  float* bb2 = (float*)sym(g_bb2);
    float* f0 = (float*)sym(g_feat0); float* f1 = (float*)sym(g_feat1);
    float* f2 = (float*)sym(g_feat2); float* f3 = (float*)sym(g_feat3);
    unsigned char* m0 = (unsigned char*)sym(g_m0);
    unsigned char* m1 = (unsigned char*)sym(g_m1);
    int* l0c = (int*)sym(g_list0cell);
    int* l1 = (int*)sym(g_list1); int* l2 = (int*)sym(g_list2);
    float* col1 = (float*)sym(g_col1); float* col2 = (float*)sym(g_col2);
    float* bev1o = (float*)sym(g_bev1);

    // 0: scatter + weight prep (state pre-zeroed by previous call's final kernel)
    scatter_prep<<<SCAT_BLOCKS + PREP_BLOCKS, 256>>>(
        points, Npts,
        sp1_w, sp1_g, sp2_w, sp2_g, sp3_w, sp3_g, sp4_w, sp4_g,
        bev1_w, bev1_g, bev2_w, bev2_g, bev1_b, bev1_be, bev2_b, bev2_be,
        vfe1_w, vfe1_b, vfe1_g, vfe1_be, vfe2_w, vfe2_b, vfe2_g, vfe2_be);
    // 1: scan
    scan_opt<<<1, 1024>>>();
    // 2: VFE
    vfe_warp<<<(MAXV + 7) / 8, 256>>>();
    // 3: spconv1  <-- profiled launch
    spconv<128, 64, 4, 32, 1, 20, 100, 100, 20, 100, 100><<<(MAXV + 31) / 32, 256>>>(
        f0, m0, w1t, sp1_be, l0c, 0, f1);
    // 4:
    pool1<<<(N1 + 255) / 256, 256>>>();
    // 5:
    spconv<64, 128, 2, 32, 2, 20, 100, 100, 10, 50, 50><<<(N1 + 31) / 32, 256>>>(
        f1, m0, w2t, sp2_be, l1, 1, f2);
    // 6:
    spconv<128, 128, 2, 32, 1, 10, 50, 50, 10, 50, 50><<<(N1 + 31) / 32, 256>>>(
        f2, m1, w3t, sp3_be, l1, 1, f3);
    // 7:
    pool2<<<(N2 + 255) / 256, 256>>>();
    // 8:
    spconv<128, 256, 1, 16, 2, 10, 50, 50, 5, 25, 25><<<(N2 + 15) / 16, 256>>>(
        f3, m1, w4t, sp4_be, l2, 2, (float*)sym(g_feat4));
    // 9:
    im2col1<<<(9 * 1280 * P2D + 255) / 256, 256>>>(col1);
    // 10-11:
    {
        dim3 g((P2D + 63) / 64, 512 / 64, 4);
        gemm_f2<512, 11520, 4><<<g, 256>>>(wb1t, col1);
        combine_bias_relu<512, 4><<<(512 * P2D + 255) / 256, 256>>>(bb1, bev1o);
    }
    // 12:
    im2col<512><<<(9 * 512 * P2D + 255) / 256, 256>>>(bev1o, col2);
    // 13:
    {
        dim3 g((P2D + 63) / 64, 256 / 64, 4);
        gemm_f2<256, 4608, 4><<<g, 256>>>(wb2t, col2);
    }
    // 14: combine2 + re-zero state for next invocation
    final_combine_zero<<<COMB2_BLOCKS + ZBLK, 256>>>(bb2, (float*)d_out);
}